// round 2
// baseline (speedup 1.0000x reference)
#include <cuda_runtime.h>
#include <cuda_bf16.h>
#include <mma.h>
#include <math.h>

using namespace nvcuda;

#define E_DIM 2048
#define B_SZ 2
#define S_LEN 2048
#define NH 16
#define DH 128
#define LDIM 64
#define M_ROWS 4096    /* B*S */

// ---------------- scratch (device globals; no runtime allocation) ----------------
__device__ float g_Q[(size_t)M_ROWS * E_DIM];
__device__ float g_K[(size_t)M_ROWS * E_DIM];
__device__ float g_V[(size_t)M_ROWS * E_DIM];
__device__ float g_QL[(size_t)B_SZ * NH * S_LEN * LDIM];
__device__ float g_KL[(size_t)B_SZ * NH * S_LEN * LDIM];
__device__ float g_AT[(size_t)B_SZ * NH * S_LEN * DH];
__device__ float g_MX[(size_t)M_ROWS * E_DIM];

__device__ __forceinline__ float gelu_tanh(float x) {
    const float c = 0.7978845608028654f;
    float x3 = x * x * x;
    return 0.5f * x * (1.f + tanhf(c * (x + 0.044715f * x3)));
}

// split a loaded fp32 fragment into tf32 hi/lo pair (3xTF32 scheme)
template <typename FragT>
__device__ __forceinline__ void tf32_split(FragT& hi, FragT& lo) {
#pragma unroll
    for (int t = 0; t < hi.num_elements; t++) {
        float v = hi.x[t];
        float h = wmma::__float_to_tf32(v);
        lo.x[t] = wmma::__float_to_tf32(v - h);
        hi.x[t] = h;
    }
}

// ---------------- generic [4096 x 2048 x 2048] 3xTF32 GEMM + bias ----------------
// C[m,n] = A[m,:] @ W[:,n] + bias[n].  A: lda=2048 row-major, W row-major [2048,2048].
__global__ __launch_bounds__(256) void gemmE_kernel(
    const float* __restrict__ A, const float* __restrict__ W,
    const float* __restrict__ bias, float* __restrict__ C)
{
    __shared__ float As[128 * 36];
    __shared__ float Bs[32 * 132];
    int tid = threadIdx.x;
    int w = tid >> 5, lane = tid & 31;
    int wr = w >> 2, wc = w & 3;            // 2 x 4 warps, warp tile 64x32
    int m0 = blockIdx.y * 128;
    int n0 = blockIdx.x * 128;

    wmma::fragment<wmma::accumulator, 16, 16, 8, float> cf[4][2];
#pragma unroll
    for (int i = 0; i < 4; i++)
#pragma unroll
        for (int j = 0; j < 2; j++) wmma::fill_fragment(cf[i][j], 0.f);

    for (int kt = 0; kt < E_DIM / 32; kt++) {
#pragma unroll
        for (int i = 0; i < 4; i++) {
            int idx = i * 256 + tid;
            int row = idx >> 3, c4 = idx & 7;
            float4 va = *reinterpret_cast<const float4*>(&A[(size_t)(m0 + row) * E_DIM + kt * 32 + c4 * 4]);
            *reinterpret_cast<float4*>(&As[row * 36 + c4 * 4]) = va;
            int rowb = idx >> 5, cb = idx & 31;
            float4 vb = *reinterpret_cast<const float4*>(&W[(size_t)(kt * 32 + rowb) * E_DIM + n0 + cb * 4]);
            *reinterpret_cast<float4*>(&Bs[rowb * 132 + cb * 4]) = vb;
        }
        __syncthreads();
#pragma unroll
        for (int ks = 0; ks < 4; ks++) {
            wmma::fragment<wmma::matrix_a, 16, 16, 8, wmma::precision::tf32, wmma::row_major> ah[4], al[4];
            wmma::fragment<wmma::matrix_b, 16, 16, 8, wmma::precision::tf32, wmma::row_major> bh[2], bl[2];
#pragma unroll
            for (int i = 0; i < 4; i++) {
                wmma::load_matrix_sync(ah[i], &As[(wr * 64 + i * 16) * 36 + ks * 8], 36);
                tf32_split(ah[i], al[i]);
            }
#pragma unroll
            for (int j = 0; j < 2; j++) {
                wmma::load_matrix_sync(bh[j], &Bs[(ks * 8) * 132 + wc * 32 + j * 16], 132);
                tf32_split(bh[j], bl[j]);
            }
#pragma unroll
            for (int i = 0; i < 4; i++)
#pragma unroll
                for (int j = 0; j < 2; j++) {
                    wmma::mma_sync(cf[i][j], al[i], bh[j], cf[i][j]);
                    wmma::mma_sync(cf[i][j], ah[i], bl[j], cf[i][j]);
                    wmma::mma_sync(cf[i][j], ah[i], bh[j], cf[i][j]);
                }
        }
        __syncthreads();
    }
    // epilogue: per-warp scratch reusing As (all reads of As are done)
    float* scratch = &As[w * 320];
#pragma unroll
    for (int i = 0; i < 4; i++)
#pragma unroll
        for (int j = 0; j < 2; j++) {
            wmma::store_matrix_sync(scratch, cf[i][j], 20, wmma::mem_row_major);
            __syncwarp();
            int gr0 = m0 + wr * 64 + i * 16;
            int gc0 = n0 + wc * 32 + j * 16;
#pragma unroll
            for (int e = lane; e < 256; e += 32) {
                int rr = e >> 4, cc = e & 15;
                float v = scratch[rr * 20 + cc] + bias[gc0 + cc];
                C[(size_t)(gr0 + rr) * E_DIM + gc0 + cc] = v;
            }
            __syncwarp();
        }
}

// ---------------- latent projection: per head, elu(q@Wl+b)+1, 3xTF32 ----------------
// grid: (mblock 32, h 16, which 2). Output layout [B,H,S,L].
__global__ __launch_bounds__(256) void lat_kernel(
    const float* __restrict__ Q, const float* __restrict__ K,
    const float* __restrict__ Wql, const float* __restrict__ bql,
    const float* __restrict__ Wkl, const float* __restrict__ bkl,
    float* __restrict__ QL, float* __restrict__ KL)
{
    __shared__ float As[128 * 36];
    __shared__ float Bs[32 * 68];
    int h = blockIdx.y;
    int which = blockIdx.z;
    const float* A = which ? K : Q;
    const float* Wl = which ? Wkl : Wql;
    const float* bl = which ? bkl : bql;
    float* C = which ? KL : QL;

    int tid = threadIdx.x, w = tid >> 5, lane = tid & 31;
    int wr = w >> 1, wc = w & 1;           // 4 x 2 warps, warp tile 32x32
    int m0 = blockIdx.x * 128;

    wmma::fragment<wmma::accumulator, 16, 16, 8, float> cf[2][2];
#pragma unroll
    for (int i = 0; i < 2; i++)
#pragma unroll
        for (int j = 0; j < 2; j++) wmma::fill_fragment(cf[i][j], 0.f);

    for (int kt = 0; kt < 4; kt++) {      // K = 128
#pragma unroll
        for (int i = 0; i < 4; i++) {
            int idx = i * 256 + tid;
            int row = idx >> 3, c4 = idx & 7;
            float4 va = *reinterpret_cast<const float4*>(&A[(size_t)(m0 + row) * E_DIM + h * DH + kt * 32 + c4 * 4]);
            *reinterpret_cast<float4*>(&As[row * 36 + c4 * 4]) = va;
        }
#pragma unroll
        for (int i = 0; i < 2; i++) {
            int idx = i * 256 + tid;     // 512 float4 of B (32x64)
            int rowb = idx >> 4, cb = idx & 15;
            float4 vb = *reinterpret_cast<const float4*>(&Wl[(size_t)(kt * 32 + rowb) * LDIM + cb * 4]);
            *reinterpret_cast<float4*>(&Bs[rowb * 68 + cb * 4]) = vb;
        }
        __syncthreads();
#pragma unroll
        for (int ks = 0; ks < 4; ks++) {
            wmma::fragment<wmma::matrix_a, 16, 16, 8, wmma::precision::tf32, wmma::row_major> ah[2], al[2];
            wmma::fragment<wmma::matrix_b, 16, 16, 8, wmma::precision::tf32, wmma::row_major> bh[2], bl2[2];
#pragma unroll
            for (int i = 0; i < 2; i++) {
                wmma::load_matrix_sync(ah[i], &As[(wr * 32 + i * 16) * 36 + ks * 8], 36);
                tf32_split(ah[i], al[i]);
            }
#pragma unroll
            for (int j = 0; j < 2; j++) {
                wmma::load_matrix_sync(bh[j], &Bs[(ks * 8) * 68 + wc * 32 + j * 16], 68);
                tf32_split(bh[j], bl2[j]);
            }
#pragma unroll
            for (int i = 0; i < 2; i++)
#pragma unroll
                for (int j = 0; j < 2; j++) {
                    wmma::mma_sync(cf[i][j], al[i], bh[j], cf[i][j]);
                    wmma::mma_sync(cf[i][j], ah[i], bl2[j], cf[i][j]);
                    wmma::mma_sync(cf[i][j], ah[i], bh[j], cf[i][j]);
                }
        }
        __syncthreads();
    }
    float* scratch = &As[w * 320];
#pragma unroll
    for (int i = 0; i < 2; i++)
#pragma unroll
        for (int j = 0; j < 2; j++) {
            wmma::store_matrix_sync(scratch, cf[i][j], 20, wmma::mem_row_major);
            __syncwarp();
#pragma unroll
            for (int e = lane; e < 256; e += 32) {
                int rr = e >> 4, cc = e & 15;
                int gr = m0 + wr * 32 + i * 16 + rr;
                int gc = wc * 32 + j * 16 + cc;
                float v = scratch[rr * 20 + cc] + bl[gc];
                v = (v > 0.f) ? (v + 1.f) : expf(v);    // elu(v)+1
                int b = gr >> 11;
                int s = gr & 2047;
                C[((size_t)(b * NH + h) * S_LEN + s) * LDIM + gc] = v;
            }
            __syncwarp();
        }
}

// ---------------- block attention (plain tf32) ----------------
// grid: (qb 16, h 16, b 2), 256 threads, dynamic smem.
#define ATTN_SMEM_FLOATS (128*68 + 128*68 + 128*136 + 128*3 + 256*2 + 128*136)
#define ATTN_SMEM_BYTES (ATTN_SMEM_FLOATS * 4)

__global__ __launch_bounds__(256) void attn_kernel(
    const float* __restrict__ QL, const float* __restrict__ KL,
    const float* __restrict__ V, float* __restrict__ OUT)
{
    extern __shared__ float sm[];
    float* qs   = sm;                   // 128 x 68 (L=64 + pad)
    float* ks   = qs + 128 * 68;        // 128 x 68
    float* Ss   = ks + 128 * 68;        // 128 x 136 (scores, then probs in place)
    float* mrow = Ss + 128 * 136;       // 128
    float* lrow = mrow + 128;           // 128
    float* mtmp = lrow + 128;           // 128
    float* pmax = mtmp + 128;           // 256
    float* psum = pmax + 256;           // 256
    float* Vs   = psum + 256;           // 128 x 136

    int tid = threadIdx.x;
    int w = tid >> 5;
    int wr = w >> 2, wc = w & 3;        // 2 x 4 warps, warp tile 64x32
    int qb = blockIdx.x, h = blockIdx.y, b = blockIdx.z;
    int bh = b * NH + h;
    const float scale = 0.125f;         // 1/sqrt(64)

    {   // q_lat tile [128 x 64]
        const float* src = QL + ((size_t)bh * S_LEN + qb * 128) * LDIM;
#pragma unroll
        for (int i = 0; i < 8; i++) {
            int idx = i * 256 + tid;
            int row = idx >> 4, c4 = idx & 15;
            float4 v4 = *reinterpret_cast<const float4*>(&src[row * LDIM + c4 * 4]);
            *reinterpret_cast<float4*>(&qs[row * 68 + c4 * 4]) = v4;
        }
    }

    wmma::fragment<wmma::accumulator, 16, 16, 8, float> acc[4][2];
#pragma unroll
    for (int i = 0; i < 4; i++)
#pragma unroll
        for (int j = 0; j < 2; j++) wmma::fill_fragment(acc[i][j], 0.f);

    for (int kv = 0; kv < 4; kv++) {
        if (tid < 128) { mrow[tid] = -1e30f; lrow[tid] = 0.f; }
        __syncthreads();

        // ---------- pass 1: row max & exp-sum over the 512-wide block ----------
        for (int c = 0; c < 4; c++) {
            const float* ksrc = KL + ((size_t)bh * S_LEN + kv * 512 + c * 128) * LDIM;
#pragma unroll
            for (int i = 0; i < 8; i++) {
                int idx = i * 256 + tid;
                int row = idx >> 4, c4 = idx & 15;
                float4 v4 = *reinterpret_cast<const float4*>(&ksrc[row * LDIM + c4 * 4]);
                *reinterpret_cast<float4*>(&ks[row * 68 + c4 * 4]) = v4;
            }
            __syncthreads();
            {   // S chunk = q @ k^T * scale  (128 x 128, K=64)
                wmma::fragment<wmma::accumulator, 16, 16, 8, float> sc[4][2];
#pragma unroll
                for (int i = 0; i < 4; i++)
#pragma unroll
                    for (int j = 0; j < 2; j++) wmma::fill_fragment(sc[i][j], 0.f);
#pragma unroll
                for (int k8 = 0; k8 < 8; k8++) {
                    wmma::fragment<wmma::matrix_a, 16, 16, 8, wmma::precision::tf32, wmma::row_major> aq[4];
                    wmma::fragment<wmma::matrix_b, 16, 16, 8, wmma::precision::tf32, wmma::col_major> bk[2];
#pragma unroll
                    for (int i = 0; i < 4; i++) {
                        wmma::load_matrix_sync(aq[i], &qs[(wr * 64 + i * 16) * 68 + k8 * 8], 68);
#pragma unroll
                        for (int t = 0; t < aq[i].num_elements; t++) aq[i].x[t] = wmma::__float_to_tf32(aq[i].x[t]);
                    }
#pragma unroll
                    for (int j = 0; j < 2; j++) {
                        wmma::load_matrix_sync(bk[j], &ks[(wc * 32 + j * 16) * 68 + k8 * 8], 68);
#pragma unroll
                        for (int t = 0; t < bk[j].num_elements; t++) bk[j].x[t] = wmma::__float_to_tf32(bk[j].x[t]);
                    }
#pragma unroll
                    for (int i = 0; i < 4; i++)
#pragma unroll
                        for (int j = 0; j < 2; j++) wmma::mma_sync(sc[i][j], aq[i], bk[j], sc[i][j]);
                }
#pragma unroll
                for (int i = 0; i < 4; i++)
#pragma unroll
                    for (int j = 0; j < 2; j++) {
#pragma unroll
                        for (int t = 0; t < sc[i][j].num_elements; t++) sc[i][j].x[t] *= scale;
                        wmma::store_matrix_sync(&Ss[(wr * 64 + i * 16) * 136 + wc * 32 + j * 16],
                                                sc[i][j], 136, wmma::mem_row_major);
                    }
            }
            __syncthreads();
            // stats: 2 threads per row
            {
                int r = tid >> 1, half = tid & 1;
                const float* Sr = Ss + r * 136 + half * 64;
                float lm = -1e30f;
#pragma unroll 8
                for (int f = 0; f < 64; f++) lm = fmaxf(lm, Sr[f]);
                pmax[tid] = lm;
                __syncthreads();
                if (tid < 128) mtmp[tid] = fmaxf(mrow[tid], fmaxf(pmax[2 * tid], pmax[2 * tid + 1]));
                __syncthreads();
                float mn = mtmp[r];
                float se = 0.f;
#pragma unroll 8
                for (int f = 0; f < 64; f++) se += __expf(Sr[f] - mn);
                psum[tid] = se;
                __syncthreads();
                if (tid < 128) {
                    float mo = mrow[tid], mn2 = mtmp[tid];
                    lrow[tid] = lrow[tid] * __expf(mo - mn2) + psum[2 * tid] + psum[2 * tid + 1];
                    mrow[tid] = mn2;
                }
                __syncthreads();
            }
        }

        // ---------- pass 2: recompute S, exp in place, P@V ----------
        for (int c = 0; c < 4; c++) {
            const float* ksrc = KL + ((size_t)bh * S_LEN + kv * 512 + c * 128) * LDIM;
#pragma unroll
            for (int i = 0; i < 8; i++) {
                int idx = i * 256 + tid;
                int row = idx >> 4, c4 = idx & 15;
                float4 v4 = *reinterpret_cast<const float4*>(&ksrc[row * LDIM + c4 * 4]);
                *reinterpret_cast<float4*>(&ks[row * 68 + c4 * 4]) = v4;
            }
            __syncthreads();
            {   // S chunk (identical recompute)
                wmma::fragment<wmma::accumulator, 16, 16, 8, float> sc[4][2];
#pragma unroll
                for (int i = 0; i < 4; i++)
#pragma unroll
                    for (int j = 0; j < 2; j++) wmma::fill_fragment(sc[i][j], 0.f);
#pragma unroll
                for (int k8 = 0; k8 < 8; k8++) {
                    wmma::fragment<wmma::matrix_a, 16, 16, 8, wmma::precision::tf32, wmma::row_major> aq[4];
                    wmma::fragment<wmma::matrix_b, 16, 16, 8, wmma::precision::tf32, wmma::col_major> bk[2];
#pragma unroll
                    for (int i = 0; i < 4; i++) {
                        wmma::load_matrix_sync(aq[i], &qs[(wr * 64 + i * 16) * 68 + k8 * 8], 68);
#pragma unroll
                        for (int t = 0; t < aq[i].num_elements; t++) aq[i].x[t] = wmma::__float_to_tf32(aq[i].x[t]);
                    }
#pragma unroll
                    for (int j = 0; j < 2; j++) {
                        wmma::load_matrix_sync(bk[j], &ks[(wc * 32 + j * 16) * 68 + k8 * 8], 68);
#pragma unroll
                        for (int t = 0; t < bk[j].num_elements; t++) bk[j].x[t] = wmma::__float_to_tf32(bk[j].x[t]);
                    }
#pragma unroll
                    for (int i = 0; i < 4; i++)
#pragma unroll
                        for (int j = 0; j < 2; j++) wmma::mma_sync(sc[i][j], aq[i], bk[j], sc[i][j]);
                }
#pragma unroll
                for (int i = 0; i < 4; i++)
#pragma unroll
                    for (int j = 0; j < 2; j++) {
#pragma unroll
                        for (int t = 0; t < sc[i][j].num_elements; t++) sc[i][j].x[t] *= scale;
                        wmma::store_matrix_sync(&Ss[(wr * 64 + i * 16) * 136 + wc * 32 + j * 16],
                                                sc[i][j], 136, wmma::mem_row_major);
                    }
            }
            __syncthreads();
            // probs in place (fp32)
            for (int idx = tid; idx < 128 * 128; idx += 256) {
                int r2 = idx >> 7, f = idx & 127;
                float p = __expf(Ss[r2 * 136 + f] - mrow[r2]);
                Ss[r2 * 136 + f] = __fdividef(p, lrow[r2]);
            }
            // V chunk [128 x 128] fp32
            {
                const float* vsrc = V + ((size_t)(b * S_LEN + kv * 512 + c * 128)) * E_DIM + h * DH;
#pragma unroll
                for (int i = 0; i < 16; i++) {
                    int idx = i * 256 + tid;
                    int row = idx >> 5, c4 = idx & 31;
                    float4 v4 = *reinterpret_cast<const float4*>(&vsrc[(size_t)row * E_DIM + c4 * 4]);
                    *reinterpret_cast<float4*>(&Vs[row * 136 + c4 * 4]) = v4;
                }
            }
            __syncthreads();
            // acc += P @ V  (128x128x128, tf32)
#pragma unroll
            for (int k8 = 0; k8 < 16; k8++) {
                wmma::fragment<wmma::matrix_a, 16, 16, 8, wmma::precision::tf32, wmma::row_major> pa[4];
                wmma::fragment<wmma::matrix_b, 16, 16, 8, wmma::precision::tf32, wmma::row_major> vb[2];
#pragma unroll
                for (int i = 0; i < 4; i++) {
                    wmma::load_matrix_sync(pa[i], &Ss[(wr * 64 + i * 16) * 136 + k8 * 8], 136);
#pragma unroll
                    for (int t = 0; t < pa[i].num_elements; t++) pa[i].x[t] = wmma::__float_to_tf32(pa[i].x[t]);
                }
#pragma unroll
                for (int j = 0; j < 2; j++) {
                    wmma::load_matrix_sync(vb[j], &Vs[(k8 * 8) * 136 + wc * 32 + j * 16], 136);
#pragma unroll
                    for (int t = 0; t < vb[j].num_elements; t++) vb[j].x[t] = wmma::__float_to_tf32(vb[j].x[t]);
                }
#pragma unroll
                for (int i = 0; i < 4; i++)
#pragma unroll
                    for (int j = 0; j < 2; j++) wmma::mma_sync(acc[i][j], pa[i], vb[j], acc[i][j]);
            }
            __syncthreads();
        }
    }
    // write attention output [B,H,S,DH]
#pragma unroll
    for (int i = 0; i < 4; i++)
#pragma unroll
        for (int j = 0; j < 2; j++) {
            float* dst = OUT + ((size_t)(bh * S_LEN + qb * 128 + wr * 64 + i * 16)) * DH + wc * 32 + j * 16;
            wmma::store_matrix_sync(dst, acc[i][j], DH, wmma::mem_row_major);
        }
}

// ---------------- mixer: gelu(AT @ Wm + bm), 3xTF32, fused head-transpose ----------------
// A: [B*H*S, 128]; out: g_MX[b, s, h*128 + n]
__global__ __launch_bounds__(256) void mixer_kernel(
    const float* __restrict__ A, const float* __restrict__ Wm,
    const float* __restrict__ bm, float* __restrict__ Cout)
{
    __shared__ float As[128 * 36];
    __shared__ float Bs[32 * 132];
    int tid = threadIdx.x, w = tid >> 5, lane = tid & 31;
    int wr = w >> 2, wc = w & 3;
    int m0 = blockIdx.x * 128;

    wmma::fragment<wmma::accumulator, 16, 16, 8, float> cf[4][2];
#pragma unroll
    for (int i = 0; i < 4; i++)
#pragma unroll
        for (int j = 0; j < 2; j++) wmma::fill_fragment(cf[i][j], 0.f);

    for (int kt = 0; kt < 4; kt++) {      // K = 128
#pragma unroll
        for (int i = 0; i < 4; i++) {
            int idx = i * 256 + tid;
            int row = idx >> 3, c4 = idx & 7;
            float4 va = *reinterpret_cast<const float4*>(&A[(size_t)(m0 + row) * DH + kt * 32 + c4 * 4]);
            *reinterpret_cast<float4*>(&As[row * 36 + c4 * 4]) = va;
            int rowb = idx >> 5, cb = idx & 31;
            float4 vb = *reinterpret_cast<const float4*>(&Wm[(size_t)(kt * 32 + rowb) * DH + cb * 4]);
            *reinterpret_cast<float4*>(&Bs[rowb * 132 + cb * 4]) = vb;
        }
        __syncthreads();
#pragma unroll
        for (int ks = 0; ks < 4; ks++) {
            wmma::fragment<wmma::matrix_a, 16, 16, 8, wmma::precision::tf32, wmma::row_major> ah[4], al[4];
            wmma::fragment<wmma::matrix_b, 16, 16, 8, wmma::precision::tf32, wmma::row_major> bh[2], bl[2];
#pragma unroll
            for (int i = 0; i < 4; i++) {
                wmma::load_matrix_sync(ah[i], &As[(wr * 64 + i * 16) * 36 + ks * 8], 36);
                tf32_split(ah[i], al[i]);
            }
#pragma unroll
            for (int j = 0; j < 2; j++) {
                wmma::load_matrix_sync(bh[j], &Bs[(ks * 8) * 132 + wc * 32 + j * 16], 132);
                tf32_split(bh[j], bl[j]);
            }
#pragma unroll
            for (int i = 0; i < 4; i++)
#pragma unroll
                for (int j = 0; j < 2; j++) {
                    wmma::mma_sync(cf[i][j], al[i], bh[j], cf[i][j]);
                    wmma::mma_sync(cf[i][j], ah[i], bl[j], cf[i][j]);
                    wmma::mma_sync(cf[i][j], ah[i], bh[j], cf[i][j]);
                }
        }
        __syncthreads();
    }
    float* scratch = &As[w * 320];
#pragma unroll
    for (int i = 0; i < 4; i++)
#pragma unroll
        for (int j = 0; j < 2; j++) {
            wmma::store_matrix_sync(scratch, cf[i][j], 20, wmma::mem_row_major);
            __syncwarp();
#pragma unroll
            for (int e = lane; e < 256; e += 32) {
                int rr = e >> 4, cc = e & 15;
                int rg = m0 + wr * 64 + i * 16 + rr;
                int gc = wc * 32 + j * 16 + cc;
                float v = gelu_tanh(scratch[rr * 20 + cc] + bm[gc]);
                int bb = rg >> 15;
                int hh = (rg >> 11) & 15;
                int ss = rg & 2047;
                Cout[((size_t)(bb * S_LEN + ss)) * E_DIM + hh * DH + gc] = v;
            }
            __syncwarp();
        }
}

// ---------------- launch ----------------
extern "C" void kernel_launch(void* const* d_in, const int* in_sizes, int n_in,
                              void* d_out, int out_size)
{
    const float* x   = (const float*)d_in[0];
    const float* Wq  = (const float*)d_in[1];
    const float* bq  = (const float*)d_in[2];
    const float* Wk  = (const float*)d_in[3];
    const float* bk  = (const float*)d_in[4];
    const float* Wv  = (const float*)d_in[5];
    const float* bv  = (const float*)d_in[6];
    const float* Wo  = (const float*)d_in[7];
    const float* bo  = (const float*)d_in[8];
    const float* Wql = (const float*)d_in[9];
    const float* bql = (const float*)d_in[10];
    const float* Wkl = (const float*)d_in[11];
    const float* bkl = (const float*)d_in[12];
    const float* Wm  = (const float*)d_in[13];
    const float* bm  = (const float*)d_in[14];
    float* out = (float*)d_out;

    float *pQ, *pK, *pV, *pQL, *pKL, *pAT, *pMX;
    cudaGetSymbolAddress((void**)&pQ,  g_Q);
    cudaGetSymbolAddress((void**)&pK,  g_K);
    cudaGetSymbolAddress((void**)&pV,  g_V);
    cudaGetSymbolAddress((void**)&pQL, g_QL);
    cudaGetSymbolAddress((void**)&pKL, g_KL);
    cudaGetSymbolAddress((void**)&pAT, g_AT);
    cudaGetSymbolAddress((void**)&pMX, g_MX);

    cudaFuncSetAttribute(attn_kernel, cudaFuncAttributeMaxDynamicSharedMemorySize, ATTN_SMEM_BYTES);

    dim3 gE(16, 32);
    gemmE_kernel<<<gE, 256>>>(x, Wq, bq, pQ);
    gemmE_kernel<<<gE, 256>>>(x, Wk, bk, pK);
    gemmE_kernel<<<gE, 256>>>(x, Wv, bv, pV);
    lat_kernel<<<dim3(32, 16, 2), 256>>>(pQ, pK, Wql, bql, Wkl, bkl, pQL, pKL);
    attn_kernel<<<dim3(16, 16, 2), 256, ATTN_SMEM_BYTES>>>(pQL, pKL, pV, pAT);
    mixer_kernel<<<dim3(512), 256>>>(pAT, Wm, bm, pMX);
    gemmE_kernel<<<gE, 256>>>(pMX, Wo, bo, out);
}

// round 4
// speedup vs baseline: 2.1973x; 2.1973x over previous
#include <cuda_runtime.h>
#include <cuda_bf16.h>
#include <mma.h>
#include <math.h>
#include <stdint.h>

using namespace nvcuda;

#define E_DIM 2048
#define B_SZ 2
#define S_LEN 2048
#define NH 16
#define DH 128
#define LDIM 64
#define M_ROWS 4096    /* B*S */

// ---------------- scratch (device globals; no runtime allocation) ----------------
__device__ float g_Q[(size_t)M_ROWS * E_DIM];
__device__ float g_K[(size_t)M_ROWS * E_DIM];
__device__ float g_V[(size_t)M_ROWS * E_DIM];
__device__ float g_QL[(size_t)B_SZ * NH * S_LEN * LDIM];
__device__ float g_KL[(size_t)B_SZ * NH * S_LEN * LDIM];
__device__ float g_AT[(size_t)B_SZ * NH * S_LEN * DH];
__device__ float g_MX[(size_t)M_ROWS * E_DIM];
__device__ __nv_bfloat16 g_Ahi[(size_t)M_ROWS * E_DIM];
__device__ __nv_bfloat16 g_Alo[(size_t)M_ROWS * E_DIM];
__device__ __nv_bfloat16 g_Wthi[(size_t)E_DIM * E_DIM];
__device__ __nv_bfloat16 g_Wtlo[(size_t)E_DIM * E_DIM];

__device__ __forceinline__ float gelu_tanh(float x) {
    const float c = 0.7978845608028654f;
    float x3 = x * x * x;
    return 0.5f * x * (1.f + tanhf(c * (x + 0.044715f * x3)));
}

__device__ __forceinline__ uint32_t smem_u32(const void* p) {
    uint32_t a;
    asm("{ .reg .u64 t; cvta.to.shared.u64 t, %1; cvt.u32.u64 %0, t; }" : "=r"(a) : "l"(p));
    return a;
}
#define CP_ASYNC16(dst, src) \
    asm volatile("cp.async.cg.shared.global [%0], [%1], 16;" :: "r"(dst), "l"(src))
#define CP_COMMIT() asm volatile("cp.async.commit_group;" ::: "memory")
#define CP_WAIT(n)  asm volatile("cp.async.wait_group %0;" :: "n"(n) : "memory")

// ================= prepass: bf16 hi/lo split (row-major) =================
__global__ __launch_bounds__(256) void xsplit_kernel(
    const float* __restrict__ src, __nv_bfloat16* __restrict__ hi, __nv_bfloat16* __restrict__ lo, int n4)
{
    int i = blockIdx.x * 256 + threadIdx.x;
    if (i >= n4) return;
    float4 v = reinterpret_cast<const float4*>(src)[i];
    __nv_bfloat16 h0 = __float2bfloat16(v.x), h1 = __float2bfloat16(v.y);
    __nv_bfloat16 h2 = __float2bfloat16(v.z), h3 = __float2bfloat16(v.w);
    __nv_bfloat16 l0 = __float2bfloat16(v.x - __bfloat162float(h0));
    __nv_bfloat16 l1 = __float2bfloat16(v.y - __bfloat162float(h1));
    __nv_bfloat16 l2 = __float2bfloat16(v.z - __bfloat162float(h2));
    __nv_bfloat16 l3 = __float2bfloat16(v.w - __bfloat162float(h3));
    __nv_bfloat162* ph = reinterpret_cast<__nv_bfloat162*>(hi) + i * 2;
    __nv_bfloat162* pl = reinterpret_cast<__nv_bfloat162*>(lo) + i * 2;
    ph[0] = __nv_bfloat162(h0, h1); ph[1] = __nv_bfloat162(h2, h3);
    pl[0] = __nv_bfloat162(l0, l1); pl[1] = __nv_bfloat162(l2, l3);
}

// ============ prepass: W [K,N] -> Wt hi/lo [N,K] bf16 transpose-split ============
__global__ __launch_bounds__(256) void wsplit_kernel(
    const float* __restrict__ W, __nv_bfloat16* __restrict__ hi, __nv_bfloat16* __restrict__ lo)
{
    __shared__ float t[32][33];
    int tx = threadIdx.x & 31, ty = threadIdx.x >> 5;  // 32 x 8
    int k0 = blockIdx.y * 32, n0 = blockIdx.x * 32;
#pragma unroll
    for (int j = 0; j < 4; j++)
        t[ty + j * 8][tx] = W[(size_t)(k0 + ty + j * 8) * E_DIM + n0 + tx];
    __syncthreads();
#pragma unroll
    for (int j = 0; j < 4; j++) {
        float v = t[tx][ty + j * 8];
        __nv_bfloat16 h = __float2bfloat16(v);
        __nv_bfloat16 l = __float2bfloat16(v - __bfloat162float(h));
        size_t o = (size_t)(n0 + ty + j * 8) * E_DIM + k0 + tx;
        hi[o] = h; lo[o] = l;
    }
}

// ============ bf16 3-term E-GEMM: C = A @ W + bias  (wmma 16x16x16) ============
// A hi/lo: [4096,2048] bf16 row-major.  Wt hi/lo: [2048(N),2048(K)] bf16 (K-major).
// CTA tile 128x128, K chunk 64, 2-stage cp.async pipeline.
#define GB_STRIDE 72                      /* bf16 elems per smem row (64 + 8 pad) */
#define GB_TILE_B (128 * GB_STRIDE * 2)   /* 18432 B */
#define GB_STAGE (4 * GB_TILE_B)          /* Ah, Al, Wh, Wl = 73728 B */
#define GB_SMEM (2 * GB_STAGE)            /* 147456 B */

__global__ __launch_bounds__(256) void gemm_bf3_kernel(
    const __nv_bfloat16* __restrict__ Ahi, const __nv_bfloat16* __restrict__ Alo,
    const __nv_bfloat16* __restrict__ Whi, const __nv_bfloat16* __restrict__ Wlo,
    const float* __restrict__ bias, float* __restrict__ C)
{
    extern __shared__ char smem[];
    uint32_t sb = smem_u32(smem);
    int tid = threadIdx.x, wid = tid >> 5, lane = tid & 31;
    int wr = wid >> 2, wc = wid & 3;         // 2 x 4 warps, warp tile 64x32
    int m0 = blockIdx.y * 128, n0 = blockIdx.x * 128;

    wmma::fragment<wmma::accumulator, 16, 16, 16, float> cf[4][2];
#pragma unroll
    for (int i = 0; i < 4; i++)
#pragma unroll
        for (int j = 0; j < 2; j++) wmma::fill_fragment(cf[i][j], 0.f);

    int row = tid >> 3;          // 0..31 within quarter-tile group
    int jj = tid & 7;            // 16B column within row

    // stage loader: 4 pieces x 128 rows x 64 bf16 (8x16B per row)
#define LOAD_PIECE(p, srcptr, rbase)                                              \
    {                                                                             \
        _Pragma("unroll")                                                         \
        for (int q = 0; q < 4; q++) {                                             \
            int r = q * 32 + row;                                                 \
            const __nv_bfloat16* sp = (srcptr) + (size_t)((rbase) + r) * E_DIM + kcn * 64 + jj * 8; \
            uint32_t dp = sb + st * GB_STAGE + (p) * GB_TILE_B + r * (GB_STRIDE * 2) + jj * 16;     \
            CP_ASYNC16(dp, sp);                                                   \
        }                                                                         \
    }

    {   // prologue: stage 0, chunk 0
        int kcn = 0, st = 0;
        LOAD_PIECE(0, Ahi, m0) LOAD_PIECE(1, Alo, m0)
        LOAD_PIECE(2, Whi, n0) LOAD_PIECE(3, Wlo, n0)
        CP_COMMIT();
    }

    for (int kc = 0; kc < 32; kc++) {
        int s = kc & 1;
        if (kc < 31) {
            int kcn = kc + 1, st = s ^ 1;
            LOAD_PIECE(0, Ahi, m0) LOAD_PIECE(1, Alo, m0)
            LOAD_PIECE(2, Whi, n0) LOAD_PIECE(3, Wlo, n0)
            CP_COMMIT();
            CP_WAIT(1);
        } else {
            CP_WAIT(0);
        }
        __syncthreads();

        const __nv_bfloat16* Ah = reinterpret_cast<const __nv_bfloat16*>(smem + s * GB_STAGE);
        const __nv_bfloat16* Al = reinterpret_cast<const __nv_bfloat16*>(smem + s * GB_STAGE + GB_TILE_B);
        const __nv_bfloat16* Wh = reinterpret_cast<const __nv_bfloat16*>(smem + s * GB_STAGE + 2 * GB_TILE_B);
        const __nv_bfloat16* Wl = reinterpret_cast<const __nv_bfloat16*>(smem + s * GB_STAGE + 3 * GB_TILE_B);

#pragma unroll
        for (int ks = 0; ks < 4; ks++) {
            wmma::fragment<wmma::matrix_a, 16, 16, 16, __nv_bfloat16, wmma::row_major> ah[4], al[4];
            wmma::fragment<wmma::matrix_b, 16, 16, 16, __nv_bfloat16, wmma::col_major> bh[2], bl[2];
#pragma unroll
            for (int i = 0; i < 4; i++) {
                wmma::load_matrix_sync(ah[i], &Ah[(wr * 64 + i * 16) * GB_STRIDE + ks * 16], GB_STRIDE);
                wmma::load_matrix_sync(al[i], &Al[(wr * 64 + i * 16) * GB_STRIDE + ks * 16], GB_STRIDE);
            }
#pragma unroll
            for (int j = 0; j < 2; j++) {
                wmma::load_matrix_sync(bh[j], &Wh[(wc * 32 + j * 16) * GB_STRIDE + ks * 16], GB_STRIDE);
                wmma::load_matrix_sync(bl[j], &Wl[(wc * 32 + j * 16) * GB_STRIDE + ks * 16], GB_STRIDE);
            }
#pragma unroll
            for (int i = 0; i < 4; i++)
#pragma unroll
                for (int j = 0; j < 2; j++) {
                    wmma::mma_sync(cf[i][j], ah[i], bl[j], cf[i][j]);
                    wmma::mma_sync(cf[i][j], al[i], bh[j], cf[i][j]);
                    wmma::mma_sync(cf[i][j], ah[i], bh[j], cf[i][j]);
                }
        }
        __syncthreads();
    }
#undef LOAD_PIECE

    // epilogue: per-warp scratch (reuse pipeline smem)
    float* scratch = reinterpret_cast<float*>(smem) + wid * 320;
#pragma unroll
    for (int i = 0; i < 4; i++)
#pragma unroll
        for (int j = 0; j < 2; j++) {
            wmma::store_matrix_sync(scratch, cf[i][j], 20, wmma::mem_row_major);
            __syncwarp();
            int gr0 = m0 + wr * 64 + i * 16;
            int gc0 = n0 + wc * 32 + j * 16;
#pragma unroll
            for (int e = lane; e < 256; e += 32) {
                int rr = e >> 4, cc = e & 15;
                float v = scratch[rr * 20 + cc] + bias[gc0 + cc];
                C[(size_t)(gr0 + rr) * E_DIM + gc0 + cc] = v;
            }
            __syncwarp();
        }
}

// ---------------- latent projection (3xTF32 wmma) ----------------
template <typename FragT>
__device__ __forceinline__ void tf32_split(FragT& hi, FragT& lo) {
#pragma unroll
    for (int t = 0; t < hi.num_elements; t++) {
        float v = hi.x[t];
        float h = wmma::__float_to_tf32(v);
        lo.x[t] = wmma::__float_to_tf32(v - h);
        hi.x[t] = h;
    }
}

__global__ __launch_bounds__(256) void lat_kernel(
    const float* __restrict__ Q, const float* __restrict__ K,
    const float* __restrict__ Wql, const float* __restrict__ bql,
    const float* __restrict__ Wkl, const float* __restrict__ bkl,
    float* __restrict__ QL, float* __restrict__ KL)
{
    __shared__ float As[128 * 36];
    __shared__ float Bs[32 * 68];
    int h = blockIdx.y;
    int which = blockIdx.z;
    const float* A = which ? K : Q;
    const float* Wl = which ? Wkl : Wql;
    const float* bl = which ? bkl : bql;
    float* C = which ? KL : QL;

    int tid = threadIdx.x, w = tid >> 5, lane = tid & 31;
    int wr = w >> 1, wc = w & 1;
    int m0 = blockIdx.x * 128;

    wmma::fragment<wmma::accumulator, 16, 16, 8, float> cf[2][2];
#pragma unroll
    for (int i = 0; i < 2; i++)
#pragma unroll
        for (int j = 0; j < 2; j++) wmma::fill_fragment(cf[i][j], 0.f);

    for (int kt = 0; kt < 4; kt++) {
#pragma unroll
        for (int i = 0; i < 4; i++) {
            int idx = i * 256 + tid;
            int row = idx >> 3, c4 = idx & 7;
            float4 va = *reinterpret_cast<const float4*>(&A[(size_t)(m0 + row) * E_DIM + h * DH + kt * 32 + c4 * 4]);
            *reinterpret_cast<float4*>(&As[row * 36 + c4 * 4]) = va;
        }
#pragma unroll
        for (int i = 0; i < 2; i++) {
            int idx = i * 256 + tid;
            int rowb = idx >> 4, cb = idx & 15;
            float4 vb = *reinterpret_cast<const float4*>(&Wl[(size_t)(kt * 32 + rowb) * LDIM + cb * 4]);
            *reinterpret_cast<float4*>(&Bs[rowb * 68 + cb * 4]) = vb;
        }
        __syncthreads();
#pragma unroll
        for (int ks = 0; ks < 4; ks++) {
            wmma::fragment<wmma::matrix_a, 16, 16, 8, wmma::precision::tf32, wmma::row_major> ah[2], al[2];
            wmma::fragment<wmma::matrix_b, 16, 16, 8, wmma::precision::tf32, wmma::row_major> bh[2], bl2[2];
#pragma unroll
            for (int i = 0; i < 2; i++) {
                wmma::load_matrix_sync(ah[i], &As[(wr * 32 + i * 16) * 36 + ks * 8], 36);
                tf32_split(ah[i], al[i]);
            }
#pragma unroll
            for (int j = 0; j < 2; j++) {
                wmma::load_matrix_sync(bh[j], &Bs[(ks * 8) * 68 + wc * 32 + j * 16], 68);
                tf32_split(bh[j], bl2[j]);
            }
#pragma unroll
            for (int i = 0; i < 2; i++)
#pragma unroll
                for (int j = 0; j < 2; j++) {
                    wmma::mma_sync(cf[i][j], al[i], bh[j], cf[i][j]);
                    wmma::mma_sync(cf[i][j], ah[i], bl2[j], cf[i][j]);
                    wmma::mma_sync(cf[i][j], ah[i], bh[j], cf[i][j]);
                }
        }
        __syncthreads();
    }
    float* scratch = &As[w * 320];
#pragma unroll
    for (int i = 0; i < 2; i++)
#pragma unroll
        for (int j = 0; j < 2; j++) {
            wmma::store_matrix_sync(scratch, cf[i][j], 20, wmma::mem_row_major);
            __syncwarp();
#pragma unroll
            for (int e = lane; e < 256; e += 32) {
                int rr = e >> 4, cc = e & 15;
                int gr = m0 + wr * 32 + i * 16 + rr;
                int gc = wc * 32 + j * 16 + cc;
                float v = scratch[rr * 20 + cc] + bl[gc];
                v = (v > 0.f) ? (v + 1.f) : expf(v);
                int b = gr >> 11;
                int s = gr & 2047;
                C[((size_t)(b * NH + h) * S_LEN + s) * LDIM + gc] = v;
            }
            __syncwarp();
        }
}

// ---------------- block attention (plain tf32 wmma) ----------------
#define ATTN_SMEM_FLOATS (128*68 + 128*68 + 128*136 + 128*3 + 256*2 + 128*136)
#define ATTN_SMEM_BYTES (ATTN_SMEM_FLOATS * 4)

__global__ __launch_bounds__(256) void attn_kernel(
    const float* __restrict__ QL, const float* __restrict__ KL,
    const float* __restrict__ V, float* __restrict__ OUT)
{
    extern __shared__ float sm[];
    float* qs   = sm;
    float* ks   = qs + 128 * 68;
    float* Ss   = ks + 128 * 68;
    float* mrow = Ss + 128 * 136;
    float* lrow = mrow + 128;
    float* mtmp = lrow + 128;
    float* pmax = mtmp + 128;
    float* psum = pmax + 256;
    float* Vs   = psum + 256;

    int tid = threadIdx.x;
    int w = tid >> 5;
    int wr = w >> 2, wc = w & 3;
    int qb = blockIdx.x, h = blockIdx.y, b = blockIdx.z;
    int bh = b * NH + h;
    const float scale = 0.125f;

    {
        const float* src = QL + ((size_t)bh * S_LEN + qb * 128) * LDIM;
#pragma unroll
        for (int i = 0; i < 8; i++) {
            int idx = i * 256 + tid;
            int row = idx >> 4, c4 = idx & 15;
            float4 v4 = *reinterpret_cast<const float4*>(&src[row * LDIM + c4 * 4]);
            *reinterpret_cast<float4*>(&qs[row * 68 + c4 * 4]) = v4;
        }
    }

    wmma::fragment<wmma::accumulator, 16, 16, 8, float> acc[4][2];
#pragma unroll
    for (int i = 0; i < 4; i++)
#pragma unroll
        for (int j = 0; j < 2; j++) wmma::fill_fragment(acc[i][j], 0.f);

    for (int kv = 0; kv < 4; kv++) {
        if (tid < 128) { mrow[tid] = -1e30f; lrow[tid] = 0.f; }
        __syncthreads();

        for (int c = 0; c < 4; c++) {
            const float* ksrc = KL + ((size_t)bh * S_LEN + kv * 512 + c * 128) * LDIM;
#pragma unroll
            for (int i = 0; i < 8; i++) {
                int idx = i * 256 + tid;
                int row = idx >> 4, c4 = idx & 15;
                float4 v4 = *reinterpret_cast<const float4*>(&ksrc[row * LDIM + c4 * 4]);
                *reinterpret_cast<float4*>(&ks[row * 68 + c4 * 4]) = v4;
            }
            __syncthreads();
            {
                wmma::fragment<wmma::accumulator, 16, 16, 8, float> sc[4][2];
#pragma unroll
                for (int i = 0; i < 4; i++)
#pragma unroll
                    for (int j = 0; j < 2; j++) wmma::fill_fragment(sc[i][j], 0.f);
#pragma unroll
                for (int k8 = 0; k8 < 8; k8++) {
                    wmma::fragment<wmma::matrix_a, 16, 16, 8, wmma::precision::tf32, wmma::row_major> aq[4];
                    wmma::fragment<wmma::matrix_b, 16, 16, 8, wmma::precision::tf32, wmma::col_major> bk[2];
#pragma unroll
                    for (int i = 0; i < 4; i++) {
                        wmma::load_matrix_sync(aq[i], &qs[(wr * 64 + i * 16) * 68 + k8 * 8], 68);
#pragma unroll
                        for (int t = 0; t < aq[i].num_elements; t++) aq[i].x[t] = wmma::__float_to_tf32(aq[i].x[t]);
                    }
#pragma unroll
                    for (int j = 0; j < 2; j++) {
                        wmma::load_matrix_sync(bk[j], &ks[(wc * 32 + j * 16) * 68 + k8 * 8], 68);
#pragma unroll
                        for (int t = 0; t < bk[j].num_elements; t++) bk[j].x[t] = wmma::__float_to_tf32(bk[j].x[t]);
                    }
#pragma unroll
                    for (int i = 0; i < 4; i++)
#pragma unroll
                        for (int j = 0; j < 2; j++) wmma::mma_sync(sc[i][j], aq[i], bk[j], sc[i][j]);
                }
#pragma unroll
                for (int i = 0; i < 4; i++)
#pragma unroll
                    for (int j = 0; j < 2; j++) {
#pragma unroll
                        for (int t = 0; t < sc[i][j].num_elements; t++) sc[i][j].x[t] *= scale;
                        wmma::store_matrix_sync(&Ss[(wr * 64 + i * 16) * 136 + wc * 32 + j * 16],
                                                sc[i][j], 136, wmma::mem_row_major);
                    }
            }
            __syncthreads();
            {
                int r = tid >> 1, half = tid & 1;
                const float* Sr = Ss + r * 136 + half * 64;
                float lm = -1e30f;
#pragma unroll 8
                for (int f = 0; f < 64; f++) lm = fmaxf(lm, Sr[f]);
                pmax[tid] = lm;
                __syncthreads();
                if (tid < 128) mtmp[tid] = fmaxf(mrow[tid], fmaxf(pmax[2 * tid], pmax[2 * tid + 1]));
                __syncthreads();
                float mn = mtmp[r];
                float se = 0.f;
#pragma unroll 8
                for (int f = 0; f < 64; f++) se += __expf(Sr[f] - mn);
                psum[tid] = se;
                __syncthreads();
                if (tid < 128) {
                    float mo = mrow[tid], mn2 = mtmp[tid];
                    lrow[tid] = lrow[tid] * __expf(mo - mn2) + psum[2 * tid] + psum[2 * tid + 1];
                    mrow[tid] = mn2;
                }
                __syncthreads();
            }
        }

        for (int c = 0; c < 4; c++) {
            const float* ksrc = KL + ((size_t)bh * S_LEN + kv * 512 + c * 128) * LDIM;
#pragma unroll
            for (int i = 0; i < 8; i++) {
                int idx = i * 256 + tid;
                int row = idx >> 4, c4 = idx & 15;
                float4 v4 = *reinterpret_cast<const float4*>(&ksrc[row * LDIM + c4 * 4]);
                *reinterpret_cast<float4*>(&ks[row * 68 + c4 * 4]) = v4;
            }
            __syncthreads();
            {
                wmma::fragment<wmma::accumulator, 16, 16, 8, float> sc[4][2];
#pragma unroll
                for (int i = 0; i < 4; i++)
#pragma unroll
                    for (int j = 0; j < 2; j++) wmma::fill_fragment(sc[i][j], 0.f);
#pragma unroll
                for (int k8 = 0; k8 < 8; k8++) {
                    wmma::fragment<wmma::matrix_a, 16, 16, 8, wmma::precision::tf32, wmma::row_major> aq[4];
                    wmma::fragment<wmma::matrix_b, 16, 16, 8, wmma::precision::tf32, wmma::col_major> bk[2];
#pragma unroll
                    for (int i = 0; i < 4; i++) {
                        wmma::load_matrix_sync(aq[i], &qs[(wr * 64 + i * 16) * 68 + k8 * 8], 68);
#pragma unroll
                        for (int t = 0; t < aq[i].num_elements; t++) aq[i].x[t] = wmma::__float_to_tf32(aq[i].x[t]);
                    }
#pragma unroll
                    for (int j = 0; j < 2; j++) {
                        wmma::load_matrix_sync(bk[j], &ks[(wc * 32 + j * 16) * 68 + k8 * 8], 68);
#pragma unroll
                        for (int t = 0; t < bk[j].num_elements; t++) bk[j].x[t] = wmma::__float_to_tf32(bk[j].x[t]);
                    }
#pragma unroll
                    for (int i = 0; i < 4; i++)
#pragma unroll
                        for (int j = 0; j < 2; j++) wmma::mma_sync(sc[i][j], aq[i], bk[j], sc[i][j]);
                }
#pragma unroll
                for (int i = 0; i < 4; i++)
#pragma unroll
                    for (int j = 0; j < 2; j++) {
#pragma unroll
                        for (int t = 0; t < sc[i][j].num_elements; t++) sc[i][j].x[t] *= scale;
                        wmma::store_matrix_sync(&Ss[(wr * 64 + i * 16) * 136 + wc * 32 + j * 16],
                                                sc[i][j], 136, wmma::mem_row_major);
                    }
            }
            __syncthreads();
            for (int idx = tid; idx < 128 * 128; idx += 256) {
                int r2 = idx >> 7, f = idx & 127;
                float p = __expf(Ss[r2 * 136 + f] - mrow[r2]);
                Ss[r2 * 136 + f] = __fdividef(p, lrow[r2]);
            }
            {
                const float* vsrc = V + ((size_t)(b * S_LEN + kv * 512 + c * 128)) * E_DIM + h * DH;
#pragma unroll
                for (int i = 0; i < 16; i++) {
                    int idx = i * 256 + tid;
                    int row = idx >> 5, c4 = idx & 31;
                    float4 v4 = *reinterpret_cast<const float4*>(&vsrc[(size_t)row * E_DIM + c4 * 4]);
                    *reinterpret_cast<float4*>(&Vs[row * 136 + c4 * 4]) = v4;
                }
            }
            __syncthreads();
#pragma unroll
            for (int k8 = 0; k8 < 16; k8++) {
                wmma::fragment<wmma::matrix_a, 16, 16, 8, wmma::precision::tf32, wmma::row_major> pa[4];
                wmma::fragment<wmma::matrix_b, 16, 16, 8, wmma::precision::tf32, wmma::row_major> vb[2];
#pragma unroll
                for (int i = 0; i < 4; i++) {
                    wmma::load_matrix_sync(pa[i], &Ss[(wr * 64 + i * 16) * 136 + k8 * 8], 136);
#pragma unroll
                    for (int t = 0; t < pa[i].num_elements; t++) pa[i].x[t] = wmma::__float_to_tf32(pa[i].x[t]);
                }
#pragma unroll
                for (int j = 0; j < 2; j++) {
                    wmma::load_matrix_sync(vb[j], &Vs[(k8 * 8) * 136 + wc * 32 + j * 16], 136);
#pragma unroll
                    for (int t = 0; t < vb[j].num_elements; t++) vb[j].x[t] = wmma::__float_to_tf32(vb[j].x[t]);
                }
#pragma unroll
                for (int i = 0; i < 4; i++)
#pragma unroll
                    for (int j = 0; j < 2; j++) wmma::mma_sync(acc[i][j], pa[i], vb[j], acc[i][j]);
            }
            __syncthreads();
        }
    }
#pragma unroll
    for (int i = 0; i < 4; i++)
#pragma unroll
        for (int j = 0; j < 2; j++) {
            float* dst = OUT + ((size_t)(bh * S_LEN + qb * 128 + wr * 64 + i * 16)) * DH + wc * 32 + j * 16;
            wmma::store_matrix_sync(dst, acc[i][j], DH, wmma::mem_row_major);
        }
}

// ---------------- mixer: gelu(AT @ Wm + bm), 3xTF32 ----------------
__global__ __launch_bounds__(256) void mixer_kernel(
    const float* __restrict__ A, const float* __restrict__ Wm,
    const float* __restrict__ bm, float* __restrict__ Cout)
{
    __shared__ float As[128 * 36];
    __shared__ float Bs[32 * 132];
    int tid = threadIdx.x, w = tid >> 5, lane = tid & 31;
    int wr = w >> 2, wc = w & 3;
    int m0 = blockIdx.x * 128;

    wmma::fragment<wmma::accumulator, 16, 16, 8, float> cf[4][2];
#pragma unroll
    for (int i = 0; i < 4; i++)
#pragma unroll
        for (int j = 0; j < 2; j++) wmma::fill_fragment(cf[i][j], 0.f);

    for (int kt = 0; kt < 4; kt++) {
#pragma unroll
        for (int i = 0; i < 4; i++) {
            int idx = i * 256 + tid;
            int row = idx >> 3, c4 = idx & 7;
            float4 va = *reinterpret_cast<const float4*>(&A[(size_t)(m0 + row) * DH + kt * 32 + c4 * 4]);
            *reinterpret_cast<float4*>(&As[row * 36 + c4 * 4]) = va;
            int rowb = idx >> 5, cb = idx & 31;
            float4 vb = *reinterpret_cast<const float4*>(&Wm[(size_t)(kt * 32 + rowb) * DH + cb * 4]);
            *reinterpret_cast<float4*>(&Bs[rowb * 132 + cb * 4]) = vb;
        }
        __syncthreads();
#pragma unroll
        for (int ks = 0; ks < 4; ks++) {
            wmma::fragment<wmma::matrix_a, 16, 16, 8, wmma::precision::tf32, wmma::row_major> ah[4], al[4];
            wmma::fragment<wmma::matrix_b, 16, 16, 8, wmma::precision::tf32, wmma::row_major> bh[2], bl[2];
#pragma unroll
            for (int i = 0; i < 4; i++) {
                wmma::load_matrix_sync(ah[i], &As[(wr * 64 + i * 16) * 36 + ks * 8], 36);
                tf32_split(ah[i], al[i]);
            }
#pragma unroll
            for (int j = 0; j < 2; j++) {
                wmma::load_matrix_sync(bh[j], &Bs[(ks * 8) * 132 + wc * 32 + j * 16], 132);
                tf32_split(bh[j], bl[j]);
            }
#pragma unroll
            for (int i = 0; i < 4; i++)
#pragma unroll
                for (int j = 0; j < 2; j++) {
                    wmma::mma_sync(cf[i][j], al[i], bh[j], cf[i][j]);
                    wmma::mma_sync(cf[i][j], ah[i], bl[j], cf[i][j]);
                    wmma::mma_sync(cf[i][j], ah[i], bh[j], cf[i][j]);
                }
        }
        __syncthreads();
    }
    float* scratch = &As[w * 320];
#pragma unroll
    for (int i = 0; i < 4; i++)
#pragma unroll
        for (int j = 0; j < 2; j++) {
            wmma::store_matrix_sync(scratch, cf[i][j], 20, wmma::mem_row_major);
            __syncwarp();
#pragma unroll
            for (int e = lane; e < 256; e += 32) {
                int rr = e >> 4, cc = e & 15;
                int rg = m0 + wr * 64 + i * 16 + rr;
                int gc = wc * 32 + j * 16 + cc;
                float v = gelu_tanh(scratch[rr * 20 + cc] + bm[gc]);
                int bb = rg >> 15;
                int hh = (rg >> 11) & 15;
                int ss = rg & 2047;
                Cout[((size_t)(bb * S_LEN + ss)) * E_DIM + hh * DH + gc] = v;
            }
            __syncwarp();
        }
}

// ---------------- launch ----------------
extern "C" void kernel_launch(void* const* d_in, const int* in_sizes, int n_in,
                              void* d_out, int out_size)
{
    const float* x   = (const float*)d_in[0];
    const float* Wq  = (const float*)d_in[1];
    const float* bq  = (const float*)d_in[2];
    const float* Wk  = (const float*)d_in[3];
    const float* bk  = (const float*)d_in[4];
    const float* Wv  = (const float*)d_in[5];
    const float* bv  = (const float*)d_in[6];
    const float* Wo  = (const float*)d_in[7];
    const float* bo  = (const float*)d_in[8];
    const float* Wql = (const float*)d_in[9];
    const float* bql = (const float*)d_in[10];
    const float* Wkl = (const float*)d_in[11];
    const float* bkl = (const float*)d_in[12];
    const float* Wm  = (const float*)d_in[13];
    const float* bm  = (const float*)d_in[14];
    float* out = (float*)d_out;

    float *pQ, *pK, *pV, *pQL, *pKL, *pAT, *pMX;
    __nv_bfloat16 *pAhi, *pAlo, *pWthi, *pWtlo;
    cudaGetSymbolAddress((void**)&pQ,  g_Q);
    cudaGetSymbolAddress((void**)&pK,  g_K);
    cudaGetSymbolAddress((void**)&pV,  g_V);
    cudaGetSymbolAddress((void**)&pQL, g_QL);
    cudaGetSymbolAddress((void**)&pKL, g_KL);
    cudaGetSymbolAddress((void**)&pAT, g_AT);
    cudaGetSymbolAddress((void**)&pMX, g_MX);
    cudaGetSymbolAddress((void**)&pAhi, g_Ahi);
    cudaGetSymbolAddress((void**)&pAlo, g_Alo);
    cudaGetSymbolAddress((void**)&pWthi, g_Wthi);
    cudaGetSymbolAddress((void**)&pWtlo, g_Wtlo);

    cudaFuncSetAttribute(attn_kernel, cudaFuncAttributeMaxDynamicSharedMemorySize, ATTN_SMEM_BYTES);
    cudaFuncSetAttribute(gemm_bf3_kernel, cudaFuncAttributeMaxDynamicSharedMemorySize, GB_SMEM);

    const int n4 = (M_ROWS * E_DIM) / 4;
    dim3 gw(64, 64), bw(256);
    dim3 gg(16, 32);

    xsplit_kernel<<<(n4 + 255) / 256, 256>>>(x, pAhi, pAlo, n4);
    wsplit_kernel<<<gw, bw>>>(Wq, pWthi, pWtlo);
    gemm_bf3_kernel<<<gg, 256, GB_SMEM>>>(pAhi, pAlo, pWthi, pWtlo, bq, pQ);
    wsplit_kernel<<<gw, bw>>>(Wk, pWthi, pWtlo);
    gemm_bf3_kernel<<<gg, 256, GB_SMEM>>>(pAhi, pAlo, pWthi, pWtlo, bk, pK);
    wsplit_kernel<<<gw, bw>>>(Wv, pWthi, pWtlo);
    gemm_bf3_kernel<<<gg, 256, GB_SMEM>>>(pAhi, pAlo, pWthi, pWtlo, bv, pV);

    lat_kernel<<<dim3(32, 16, 2), 256>>>(pQ, pK, Wql, bql, Wkl, bkl, pQL, pKL);
    attn_kernel<<<dim3(16, 16, 2), 256, ATTN_SMEM_BYTES>>>(pQL, pKL, pV, pAT);
    mixer_kernel<<<dim3(512), 256>>>(pAT, Wm, bm, pMX);

    xsplit_kernel<<<(n4 + 255) / 256, 256>>>(pMX, pAhi, pAlo, n4);
    wsplit_kernel<<<gw, bw>>>(Wo, pWthi, pWtlo);
    gemm_bf3_kernel<<<gg, 256, GB_SMEM>>>(pAhi, pAlo, pWthi, pWtlo, bo, out);
}

// round 5
// speedup vs baseline: 3.3791x; 1.5378x over previous
#include <cuda_runtime.h>
#include <cuda_bf16.h>
#include <mma.h>
#include <math.h>
#include <stdint.h>

using namespace nvcuda;

#define E_DIM 2048
#define B_SZ 2
#define S_LEN 2048
#define NH 16
#define DH 128
#define LDIM 64
#define M_ROWS 4096    /* B*S */

// ---------------- scratch (device globals; no runtime allocation) ----------------
__device__ float g_Q[(size_t)M_ROWS * E_DIM];
__device__ float g_K[(size_t)M_ROWS * E_DIM];
__device__ float g_V[(size_t)M_ROWS * E_DIM];
__device__ float g_QL[(size_t)B_SZ * NH * S_LEN * LDIM];
__device__ float g_KL[(size_t)B_SZ * NH * S_LEN * LDIM];
__device__ float g_AT[(size_t)B_SZ * NH * S_LEN * DH];
__device__ float g_MX[(size_t)M_ROWS * E_DIM];
__device__ __nv_bfloat16 g_Ahi[(size_t)M_ROWS * E_DIM];
__device__ __nv_bfloat16 g_Alo[(size_t)M_ROWS * E_DIM];
__device__ __nv_bfloat16 g_Wthi[(size_t)E_DIM * E_DIM];
__device__ __nv_bfloat16 g_Wtlo[(size_t)E_DIM * E_DIM];

__device__ __forceinline__ float gelu_tanh(float x) {
    const float c = 0.7978845608028654f;
    float x3 = x * x * x;
    return 0.5f * x * (1.f + tanhf(c * (x + 0.044715f * x3)));
}

__device__ __forceinline__ uint32_t smem_u32(const void* p) {
    uint32_t a;
    asm("{ .reg .u64 t; cvta.to.shared.u64 t, %1; cvt.u32.u64 %0, t; }" : "=r"(a) : "l"(p));
    return a;
}
#define CP_ASYNC16(dst, src) \
    asm volatile("cp.async.cg.shared.global [%0], [%1], 16;" :: "r"(dst), "l"(src))
#define CP_COMMIT() asm volatile("cp.async.commit_group;" ::: "memory")
#define CP_WAIT(n)  asm volatile("cp.async.wait_group %0;" :: "n"(n) : "memory")

__device__ __forceinline__ float tf32r(float x) {
    uint32_t u;
    asm("cvt.rna.tf32.f32 %0, %1;" : "=r"(u) : "f"(x));
    return __uint_as_float(u);
}

#define MMA_TF32(c, a0, a1, a2, a3, b0, b1) \
    asm volatile("mma.sync.aligned.m16n8k8.row.col.f32.tf32.tf32.f32 " \
        "{%0,%1,%2,%3}, {%4,%5,%6,%7}, {%8,%9}, {%0,%1,%2,%3};" \
        : "+f"((c)[0]), "+f"((c)[1]), "+f"((c)[2]), "+f"((c)[3]) \
        : "r"(a0), "r"(a1), "r"(a2), "r"(a3), "r"(b0), "r"(b1))

// ================= prepass: bf16 hi/lo split (row-major) =================
__global__ __launch_bounds__(256) void xsplit_kernel(
    const float* __restrict__ src, __nv_bfloat16* __restrict__ hi, __nv_bfloat16* __restrict__ lo, int n4)
{
    int i = blockIdx.x * 256 + threadIdx.x;
    if (i >= n4) return;
    float4 v = reinterpret_cast<const float4*>(src)[i];
    __nv_bfloat16 h0 = __float2bfloat16(v.x), h1 = __float2bfloat16(v.y);
    __nv_bfloat16 h2 = __float2bfloat16(v.z), h3 = __float2bfloat16(v.w);
    __nv_bfloat16 l0 = __float2bfloat16(v.x - __bfloat162float(h0));
    __nv_bfloat16 l1 = __float2bfloat16(v.y - __bfloat162float(h1));
    __nv_bfloat16 l2 = __float2bfloat16(v.z - __bfloat162float(h2));
    __nv_bfloat16 l3 = __float2bfloat16(v.w - __bfloat162float(h3));
    __nv_bfloat162* ph = reinterpret_cast<__nv_bfloat162*>(hi) + i * 2;
    __nv_bfloat162* pl = reinterpret_cast<__nv_bfloat162*>(lo) + i * 2;
    ph[0] = __nv_bfloat162(h0, h1); ph[1] = __nv_bfloat162(h2, h3);
    pl[0] = __nv_bfloat162(l0, l1); pl[1] = __nv_bfloat162(l2, l3);
}

// ============ prepass: W [K,N] -> Wt hi/lo [N,K] bf16 transpose-split ============
__global__ __launch_bounds__(256) void wsplit_kernel(
    const float* __restrict__ W, __nv_bfloat16* __restrict__ hi, __nv_bfloat16* __restrict__ lo)
{
    __shared__ float t[32][33];
    int tx = threadIdx.x & 31, ty = threadIdx.x >> 5;  // 32 x 8
    int k0 = blockIdx.y * 32, n0 = blockIdx.x * 32;
#pragma unroll
    for (int j = 0; j < 4; j++)
        t[ty + j * 8][tx] = W[(size_t)(k0 + ty + j * 8) * E_DIM + n0 + tx];
    __syncthreads();
#pragma unroll
    for (int j = 0; j < 4; j++) {
        float v = t[tx][ty + j * 8];
        __nv_bfloat16 h = __float2bfloat16(v);
        __nv_bfloat16 l = __float2bfloat16(v - __bfloat162float(h));
        size_t o = (size_t)(n0 + ty + j * 8) * E_DIM + k0 + tx;
        hi[o] = h; lo[o] = l;
    }
}

// ================= prepass: round V to tf32 in place =================
__global__ __launch_bounds__(256) void vround_kernel(float* __restrict__ v, int n4)
{
    int i = blockIdx.x * 256 + threadIdx.x;
    if (i >= n4) return;
    float4 x = reinterpret_cast<float4*>(v)[i];
    x.x = tf32r(x.x); x.y = tf32r(x.y); x.z = tf32r(x.z); x.w = tf32r(x.w);
    reinterpret_cast<float4*>(v)[i] = x;
}

// ============ bf16 3-term E-GEMM: C = A @ W + bias  (wmma 16x16x16) ============
#define GB_STRIDE 72
#define GB_TILE_B (128 * GB_STRIDE * 2)
#define GB_STAGE (4 * GB_TILE_B)
#define GB_SMEM (2 * GB_STAGE)

__global__ __launch_bounds__(256) void gemm_bf3_kernel(
    const __nv_bfloat16* __restrict__ Ahi, const __nv_bfloat16* __restrict__ Alo,
    const __nv_bfloat16* __restrict__ Whi, const __nv_bfloat16* __restrict__ Wlo,
    const float* __restrict__ bias, float* __restrict__ C)
{
    extern __shared__ char smem[];
    uint32_t sb = smem_u32(smem);
    int tid = threadIdx.x, wid = tid >> 5, lane = tid & 31;
    int wr = wid >> 2, wc = wid & 3;
    int m0 = blockIdx.y * 128, n0 = blockIdx.x * 128;

    wmma::fragment<wmma::accumulator, 16, 16, 16, float> cf[4][2];
#pragma unroll
    for (int i = 0; i < 4; i++)
#pragma unroll
        for (int j = 0; j < 2; j++) wmma::fill_fragment(cf[i][j], 0.f);

    int row = tid >> 3;
    int jj = tid & 7;

#define LOAD_PIECE(p, srcptr, rbase)                                              \
    {                                                                             \
        _Pragma("unroll")                                                         \
        for (int q = 0; q < 4; q++) {                                             \
            int r = q * 32 + row;                                                 \
            const __nv_bfloat16* sp = (srcptr) + (size_t)((rbase) + r) * E_DIM + kcn * 64 + jj * 8; \
            uint32_t dp = sb + st * GB_STAGE + (p) * GB_TILE_B + r * (GB_STRIDE * 2) + jj * 16;     \
            CP_ASYNC16(dp, sp);                                                   \
        }                                                                         \
    }

    {
        int kcn = 0, st = 0;
        LOAD_PIECE(0, Ahi, m0) LOAD_PIECE(1, Alo, m0)
        LOAD_PIECE(2, Whi, n0) LOAD_PIECE(3, Wlo, n0)
        CP_COMMIT();
    }

    for (int kc = 0; kc < 32; kc++) {
        int s = kc & 1;
        if (kc < 31) {
            int kcn = kc + 1, st = s ^ 1;
            LOAD_PIECE(0, Ahi, m0) LOAD_PIECE(1, Alo, m0)
            LOAD_PIECE(2, Whi, n0) LOAD_PIECE(3, Wlo, n0)
            CP_COMMIT();
            CP_WAIT(1);
        } else {
            CP_WAIT(0);
        }
        __syncthreads();

        const __nv_bfloat16* Ah = reinterpret_cast<const __nv_bfloat16*>(smem + s * GB_STAGE);
        const __nv_bfloat16* Al = reinterpret_cast<const __nv_bfloat16*>(smem + s * GB_STAGE + GB_TILE_B);
        const __nv_bfloat16* Wh = reinterpret_cast<const __nv_bfloat16*>(smem + s * GB_STAGE + 2 * GB_TILE_B);
        const __nv_bfloat16* Wl = reinterpret_cast<const __nv_bfloat16*>(smem + s * GB_STAGE + 3 * GB_TILE_B);

#pragma unroll
        for (int ks = 0; ks < 4; ks++) {
            wmma::fragment<wmma::matrix_a, 16, 16, 16, __nv_bfloat16, wmma::row_major> ah[4], al[4];
            wmma::fragment<wmma::matrix_b, 16, 16, 16, __nv_bfloat16, wmma::col_major> bh[2], bl[2];
#pragma unroll
            for (int i = 0; i < 4; i++) {
                wmma::load_matrix_sync(ah[i], &Ah[(wr * 64 + i * 16) * GB_STRIDE + ks * 16], GB_STRIDE);
                wmma::load_matrix_sync(al[i], &Al[(wr * 64 + i * 16) * GB_STRIDE + ks * 16], GB_STRIDE);
            }
#pragma unroll
            for (int j = 0; j < 2; j++) {
                wmma::load_matrix_sync(bh[j], &Wh[(wc * 32 + j * 16) * GB_STRIDE + ks * 16], GB_STRIDE);
                wmma::load_matrix_sync(bl[j], &Wl[(wc * 32 + j * 16) * GB_STRIDE + ks * 16], GB_STRIDE);
            }
#pragma unroll
            for (int i = 0; i < 4; i++)
#pragma unroll
                for (int j = 0; j < 2; j++) {
                    wmma::mma_sync(cf[i][j], ah[i], bl[j], cf[i][j]);
                    wmma::mma_sync(cf[i][j], al[i], bh[j], cf[i][j]);
                    wmma::mma_sync(cf[i][j], ah[i], bh[j], cf[i][j]);
                }
        }
        __syncthreads();
    }
#undef LOAD_PIECE

    float* scratch = reinterpret_cast<float*>(smem) + wid * 320;
#pragma unroll
    for (int i = 0; i < 4; i++)
#pragma unroll
        for (int j = 0; j < 2; j++) {
            wmma::store_matrix_sync(scratch, cf[i][j], 20, wmma::mem_row_major);
            __syncwarp();
            int gr0 = m0 + wr * 64 + i * 16;
            int gc0 = n0 + wc * 32 + j * 16;
#pragma unroll
            for (int e = lane; e < 256; e += 32) {
                int rr = e >> 4, cc = e & 15;
                float v = scratch[rr * 20 + cc] + bias[gc0 + cc];
                C[(size_t)(gr0 + rr) * E_DIM + gc0 + cc] = v;
            }
            __syncwarp();
        }
}

// ---------------- latent projection (3xTF32 wmma) ----------------
// Epilogue: elu+1, fold 0.125 score scale into QL, round both to tf32.
template <typename FragT>
__device__ __forceinline__ void tf32_split(FragT& hi, FragT& lo) {
#pragma unroll
    for (int t = 0; t < hi.num_elements; t++) {
        float v = hi.x[t];
        float h = wmma::__float_to_tf32(v);
        lo.x[t] = wmma::__float_to_tf32(v - h);
        hi.x[t] = h;
    }
}

__global__ __launch_bounds__(256) void lat_kernel(
    const float* __restrict__ Q, const float* __restrict__ K,
    const float* __restrict__ Wql, const float* __restrict__ bql,
    const float* __restrict__ Wkl, const float* __restrict__ bkl,
    float* __restrict__ QL, float* __restrict__ KL)
{
    __shared__ float As[128 * 36];
    __shared__ float Bs[32 * 68];
    int h = blockIdx.y;
    int which = blockIdx.z;
    const float* A = which ? K : Q;
    const float* Wl = which ? Wkl : Wql;
    const float* bl = which ? bkl : bql;
    float* C = which ? KL : QL;

    int tid = threadIdx.x, w = tid >> 5, lane = tid & 31;
    int wr = w >> 1, wc = w & 1;
    int m0 = blockIdx.x * 128;

    wmma::fragment<wmma::accumulator, 16, 16, 8, float> cf[2][2];
#pragma unroll
    for (int i = 0; i < 2; i++)
#pragma unroll
        for (int j = 0; j < 2; j++) wmma::fill_fragment(cf[i][j], 0.f);

    for (int kt = 0; kt < 4; kt++) {
#pragma unroll
        for (int i = 0; i < 4; i++) {
            int idx = i * 256 + tid;
            int row = idx >> 3, c4 = idx & 7;
            float4 va = *reinterpret_cast<const float4*>(&A[(size_t)(m0 + row) * E_DIM + h * DH + kt * 32 + c4 * 4]);
            *reinterpret_cast<float4*>(&As[row * 36 + c4 * 4]) = va;
        }
#pragma unroll
        for (int i = 0; i < 2; i++) {
            int idx = i * 256 + tid;
            int rowb = idx >> 4, cb = idx & 15;
            float4 vb = *reinterpret_cast<const float4*>(&Wl[(size_t)(kt * 32 + rowb) * LDIM + cb * 4]);
            *reinterpret_cast<float4*>(&Bs[rowb * 68 + cb * 4]) = vb;
        }
        __syncthreads();
#pragma unroll
        for (int ks = 0; ks < 4; ks++) {
            wmma::fragment<wmma::matrix_a, 16, 16, 8, wmma::precision::tf32, wmma::row_major> ah[2], al[2];
            wmma::fragment<wmma::matrix_b, 16, 16, 8, wmma::precision::tf32, wmma::row_major> bh[2], bl2[2];
#pragma unroll
            for (int i = 0; i < 2; i++) {
                wmma::load_matrix_sync(ah[i], &As[(wr * 32 + i * 16) * 36 + ks * 8], 36);
                tf32_split(ah[i], al[i]);
            }
#pragma unroll
            for (int j = 0; j < 2; j++) {
                wmma::load_matrix_sync(bh[j], &Bs[(ks * 8) * 68 + wc * 32 + j * 16], 68);
                tf32_split(bh[j], bl2[j]);
            }
#pragma unroll
            for (int i = 0; i < 2; i++)
#pragma unroll
                for (int j = 0; j < 2; j++) {
                    wmma::mma_sync(cf[i][j], al[i], bh[j], cf[i][j]);
                    wmma::mma_sync(cf[i][j], ah[i], bl2[j], cf[i][j]);
                    wmma::mma_sync(cf[i][j], ah[i], bh[j], cf[i][j]);
                }
        }
        __syncthreads();
    }
    float* scratch = &As[w * 320];
    float qscale = which ? 1.0f : 0.125f;
#pragma unroll
    for (int i = 0; i < 2; i++)
#pragma unroll
        for (int j = 0; j < 2; j++) {
            wmma::store_matrix_sync(scratch, cf[i][j], 20, wmma::mem_row_major);
            __syncwarp();
#pragma unroll
            for (int e = lane; e < 256; e += 32) {
                int rr = e >> 4, cc = e & 15;
                int gr = m0 + wr * 32 + i * 16 + rr;
                int gc = wc * 32 + j * 16 + cc;
                float v = scratch[rr * 20 + cc] + bl[gc];
                v = (v > 0.f) ? (v + 1.f) : expf(v);
                v = tf32r(v * qscale);
                int b = gr >> 11;
                int s = gr & 2047;
                C[((size_t)(b * NH + h) * S_LEN + s) * LDIM + gc] = v;
            }
            __syncwarp();
        }
}

// ================ single-pass flash attention (raw mma.sync tf32) ================
// All scores >= 0 (elu+1 features): softmax computed WITHOUT max subtraction.
// QL pre-scaled by 0.125 and tf32-rounded; KL, V tf32-rounded by producers.
// grid (qb 16, h 16, b 2), 256 threads / 8 warps; warp = 16 q rows.
// Chunks of 64 kv cols; per kv block (8 chunks): out += acc / l.
#define AT_QS 0
#define AT_KS (128 * 68)                    /* 8704 floats */
#define AT_VS (AT_KS + 2 * 64 * 68)         /* + 8704 */
#define AT_PS (AT_VS + 2 * 64 * 136)        /* + 17408 */
#define AT_TOT (AT_PS + 128 * 68)           /* 43520 floats */
#define AT_SMEM_B (AT_TOT * 4)

__global__ __launch_bounds__(256) void attn2_kernel(
    const float* __restrict__ QL, const float* __restrict__ KL,
    const float* __restrict__ V, float* __restrict__ OUT)
{
    extern __shared__ float sm[];
    float* qs  = sm;
    float* ksb = sm + AT_KS;
    float* vsb = sm + AT_VS;
    float* Ps  = sm + AT_PS;
    uint32_t sbase = smem_u32(sm);

    int tid = threadIdx.x, w = tid >> 5, lane = tid & 31;
    int g = lane >> 2, t = lane & 3;
    int wrow = w * 16;
    int qb = blockIdx.x, h = blockIdx.y, b = blockIdx.z;
    int bh = b * NH + h;

    // load q tile [128 x 64] (already scaled + tf32-rounded)
    {
        const float* qsrc = QL + ((size_t)bh * S_LEN + qb * 128) * LDIM;
#pragma unroll
        for (int i = 0; i < 8; i++) {
            int idx = i * 256 + tid;
            int r = idx >> 4, c4 = idx & 15;
            float4 v4 = *reinterpret_cast<const float4*>(&qsrc[r * LDIM + c4 * 4]);
            *reinterpret_cast<float4*>(&qs[r * 68 + c4 * 4]) = v4;
        }
    }

#define AT_PREFETCH(ci, bf)                                                           \
    {                                                                                 \
        _Pragma("unroll")                                                             \
        for (int i = 0; i < 4; i++) {                                                 \
            int idx = i * 256 + tid;                                                  \
            int r = idx >> 4, c = idx & 15;                                           \
            uint32_t dp = sbase + (uint32_t)(AT_KS + (bf) * 64 * 68 + r * 68 + c * 4) * 4; \
            CP_ASYNC16(dp, KL + ((size_t)bh * S_LEN + (ci) * 64 + r) * LDIM + c * 4); \
        }                                                                             \
        _Pragma("unroll")                                                             \
        for (int i = 0; i < 8; i++) {                                                 \
            int idx = i * 256 + tid;                                                  \
            int r = idx >> 5, c = idx & 31;                                           \
            uint32_t dp = sbase + (uint32_t)(AT_VS + (bf) * 64 * 136 + r * 136 + c * 4) * 4; \
            CP_ASYNC16(dp, V + ((size_t)(b * S_LEN + (ci) * 64 + r)) * E_DIM + h * DH + c * 4); \
        }                                                                             \
    }

    AT_PREFETCH(0, 0)
    CP_COMMIT();

    float ot[16][4], ob[16][4];
#pragma unroll
    for (int n = 0; n < 16; n++)
#pragma unroll
        for (int j = 0; j < 4; j++) { ot[n][j] = 0.f; ob[n][j] = 0.f; }
    float l0 = 0.f, l1 = 0.f;

    for (int ci = 0; ci < 32; ci++) {
        int buf = ci & 1;
        CP_WAIT(0);
        __syncthreads();
        if (ci < 31) {
            AT_PREFETCH(ci + 1, buf ^ 1)
            CP_COMMIT();
        }
        const float* ks  = ksb + buf * 64 * 68;
        const float* vsx = vsb + buf * 64 * 136;

        // ---- scores: S[16w rows][64 cols], K dim = 64 ----
        float c[8][4];
#pragma unroll
        for (int n = 0; n < 8; n++)
#pragma unroll
            for (int j = 0; j < 4; j++) c[n][j] = 0.f;
#pragma unroll
        for (int kk = 0; kk < 8; kk++) {
            int ko = kk * 8 + t;
            uint32_t a0 = __float_as_uint(qs[(wrow + g) * 68 + ko]);
            uint32_t a1 = __float_as_uint(qs[(wrow + 8 + g) * 68 + ko]);
            uint32_t a2 = __float_as_uint(qs[(wrow + g) * 68 + ko + 4]);
            uint32_t a3 = __float_as_uint(qs[(wrow + 8 + g) * 68 + ko + 4]);
#pragma unroll
            for (int n = 0; n < 8; n++) {
                uint32_t b0 = __float_as_uint(ks[(n * 8 + g) * 68 + ko]);
                uint32_t b1 = __float_as_uint(ks[(n * 8 + g) * 68 + ko + 4]);
                MMA_TF32(c[n], a0, a1, a2, a3, b0, b1);
            }
        }
        // ---- exp (no max needed: scores >= 0, bounded), P to smem, l accum ----
#pragma unroll
        for (int n = 0; n < 8; n++) {
            float p0 = __expf(c[n][0]), p1 = __expf(c[n][1]);
            float p2 = __expf(c[n][2]), p3 = __expf(c[n][3]);
            l0 += p0 + p1; l1 += p2 + p3;
            float2 u0 = make_float2(tf32r(p0), tf32r(p1));
            float2 u1 = make_float2(tf32r(p2), tf32r(p3));
            *reinterpret_cast<float2*>(&Ps[(wrow + g) * 68 + n * 8 + 2 * t]) = u0;
            *reinterpret_cast<float2*>(&Ps[(wrow + 8 + g) * 68 + n * 8 + 2 * t]) = u1;
        }
        __syncthreads();
        // ---- P @ V : [16 rows][128 out cols], K dim = 64 ----
#pragma unroll
        for (int kk = 0; kk < 8; kk++) {
            int ko = kk * 8 + t;
            uint32_t a0 = __float_as_uint(Ps[(wrow + g) * 68 + ko]);
            uint32_t a1 = __float_as_uint(Ps[(wrow + 8 + g) * 68 + ko]);
            uint32_t a2 = __float_as_uint(Ps[(wrow + g) * 68 + ko + 4]);
            uint32_t a3 = __float_as_uint(Ps[(wrow + 8 + g) * 68 + ko + 4]);
#pragma unroll
            for (int n = 0; n < 16; n++) {
                uint32_t b0 = __float_as_uint(vsx[ko * 136 + n * 8 + g]);
                uint32_t b1 = __float_as_uint(vsx[(ko + 4) * 136 + n * 8 + g]);
                MMA_TF32(ob[n], a0, a1, a2, a3, b0, b1);
            }
        }
        // ---- kv block boundary: normalize and fold into total ----
        if ((ci & 7) == 7) {
            l0 += __shfl_xor_sync(0xFFFFFFFFu, l0, 1);
            l0 += __shfl_xor_sync(0xFFFFFFFFu, l0, 2);
            l1 += __shfl_xor_sync(0xFFFFFFFFu, l1, 1);
            l1 += __shfl_xor_sync(0xFFFFFFFFu, l1, 2);
            float i0 = 1.f / l0, i1 = 1.f / l1;
#pragma unroll
            for (int n = 0; n < 16; n++) {
                ot[n][0] += ob[n][0] * i0; ot[n][1] += ob[n][1] * i0;
                ot[n][2] += ob[n][2] * i1; ot[n][3] += ob[n][3] * i1;
                ob[n][0] = 0.f; ob[n][1] = 0.f; ob[n][2] = 0.f; ob[n][3] = 0.f;
            }
            l0 = 0.f; l1 = 0.f;
        }
    }
#undef AT_PREFETCH

    // write out [B,H,S,DH]
    {
        size_t row0 = (size_t)bh * S_LEN + qb * 128 + wrow + g;
#pragma unroll
        for (int n = 0; n < 16; n++) {
            *reinterpret_cast<float2*>(&OUT[row0 * DH + n * 8 + 2 * t]) =
                make_float2(ot[n][0], ot[n][1]);
            *reinterpret_cast<float2*>(&OUT[(row0 + 8) * DH + n * 8 + 2 * t]) =
                make_float2(ot[n][2], ot[n][3]);
        }
    }
}

// ---------------- mixer: gelu(AT @ Wm + bm), 3xTF32 ----------------
__global__ __launch_bounds__(256) void mixer_kernel(
    const float* __restrict__ A, const float* __restrict__ Wm,
    const float* __restrict__ bm, float* __restrict__ Cout)
{
    __shared__ float As[128 * 36];
    __shared__ float Bs[32 * 132];
    int tid = threadIdx.x, w = tid >> 5, lane = tid & 31;
    int wr = w >> 2, wc = w & 3;
    int m0 = blockIdx.x * 128;

    wmma::fragment<wmma::accumulator, 16, 16, 8, float> cf[4][2];
#pragma unroll
    for (int i = 0; i < 4; i++)
#pragma unroll
        for (int j = 0; j < 2; j++) wmma::fill_fragment(cf[i][j], 0.f);

    for (int kt = 0; kt < 4; kt++) {
#pragma unroll
        for (int i = 0; i < 4; i++) {
            int idx = i * 256 + tid;
            int row = idx >> 3, c4 = idx & 7;
            float4 va = *reinterpret_cast<const float4*>(&A[(size_t)(m0 + row) * DH + kt * 32 + c4 * 4]);
            *reinterpret_cast<float4*>(&As[row * 36 + c4 * 4]) = va;
            int rowb = idx >> 5, cb = idx & 31;
            float4 vb = *reinterpret_cast<const float4*>(&Wm[(size_t)(kt * 32 + rowb) * DH + cb * 4]);
            *reinterpret_cast<float4*>(&Bs[rowb * 132 + cb * 4]) = vb;
        }
        __syncthreads();
#pragma unroll
        for (int ks = 0; ks < 4; ks++) {
            wmma::fragment<wmma::matrix_a, 16, 16, 8, wmma::precision::tf32, wmma::row_major> ah[4], al[4];
            wmma::fragment<wmma::matrix_b, 16, 16, 8, wmma::precision::tf32, wmma::row_major> bh[2], bl[2];
#pragma unroll
            for (int i = 0; i < 4; i++) {
                wmma::load_matrix_sync(ah[i], &As[(wr * 64 + i * 16) * 36 + ks * 8], 36);
                tf32_split(ah[i], al[i]);
            }
#pragma unroll
            for (int j = 0; j < 2; j++) {
                wmma::load_matrix_sync(bh[j], &Bs[(ks * 8) * 132 + wc * 32 + j * 16], 132);
                tf32_split(bh[j], bl[j]);
            }
#pragma unroll
            for (int i = 0; i < 4; i++)
#pragma unroll
                for (int j = 0; j < 2; j++) {
                    wmma::mma_sync(cf[i][j], al[i], bh[j], cf[i][j]);
                    wmma::mma_sync(cf[i][j], ah[i], bl[j], cf[i][j]);
                    wmma::mma_sync(cf[i][j], ah[i], bh[j], cf[i][j]);
                }
        }
        __syncthreads();
    }
    float* scratch = &As[w * 320];
#pragma unroll
    for (int i = 0; i < 4; i++)
#pragma unroll
        for (int j = 0; j < 2; j++) {
            wmma::store_matrix_sync(scratch, cf[i][j], 20, wmma::mem_row_major);
            __syncwarp();
#pragma unroll
            for (int e = lane; e < 256; e += 32) {
                int rr = e >> 4, cc = e & 15;
                int rg = m0 + wr * 64 + i * 16 + rr;
                int gc = wc * 32 + j * 16 + cc;
                float v = gelu_tanh(scratch[rr * 20 + cc] + bm[gc]);
                int bb = rg >> 15;
                int hh = (rg >> 11) & 15;
                int ss = rg & 2047;
                Cout[((size_t)(bb * S_LEN + ss)) * E_DIM + hh * DH + gc] = v;
            }
            __syncwarp();
        }
}

// ---------------- launch ----------------
extern "C" void kernel_launch(void* const* d_in, const int* in_sizes, int n_in,
                              void* d_out, int out_size)
{
    const float* x   = (const float*)d_in[0];
    const float* Wq  = (const float*)d_in[1];
    const float* bq  = (const float*)d_in[2];
    const float* Wk  = (const float*)d_in[3];
    const float* bk  = (const float*)d_in[4];
    const float* Wv  = (const float*)d_in[5];
    const float* bv  = (const float*)d_in[6];
    const float* Wo  = (const float*)d_in[7];
    const float* bo  = (const float*)d_in[8];
    const float* Wql = (const float*)d_in[9];
    const float* bql = (const float*)d_in[10];
    const float* Wkl = (const float*)d_in[11];
    const float* bkl = (const float*)d_in[12];
    const float* Wm  = (const float*)d_in[13];
    const float* bm  = (const float*)d_in[14];
    float* out = (float*)d_out;

    float *pQ, *pK, *pV, *pQL, *pKL, *pAT, *pMX;
    __nv_bfloat16 *pAhi, *pAlo, *pWthi, *pWtlo;
    cudaGetSymbolAddress((void**)&pQ,  g_Q);
    cudaGetSymbolAddress((void**)&pK,  g_K);
    cudaGetSymbolAddress((void**)&pV,  g_V);
    cudaGetSymbolAddress((void**)&pQL, g_QL);
    cudaGetSymbolAddress((void**)&pKL, g_KL);
    cudaGetSymbolAddress((void**)&pAT, g_AT);
    cudaGetSymbolAddress((void**)&pMX, g_MX);
    cudaGetSymbolAddress((void**)&pAhi, g_Ahi);
    cudaGetSymbolAddress((void**)&pAlo, g_Alo);
    cudaGetSymbolAddress((void**)&pWthi, g_Wthi);
    cudaGetSymbolAddress((void**)&pWtlo, g_Wtlo);

    cudaFuncSetAttribute(attn2_kernel, cudaFuncAttributeMaxDynamicSharedMemorySize, AT_SMEM_B);
    cudaFuncSetAttribute(gemm_bf3_kernel, cudaFuncAttributeMaxDynamicSharedMemorySize, GB_SMEM);

    const int n4 = (M_ROWS * E_DIM) / 4;
    dim3 gw(64, 64), bw(256);
    dim3 gg(16, 32);

    xsplit_kernel<<<(n4 + 255) / 256, 256>>>(x, pAhi, pAlo, n4);
    wsplit_kernel<<<gw, bw>>>(Wq, pWthi, pWtlo);
    gemm_bf3_kernel<<<gg, 256, GB_SMEM>>>(pAhi, pAlo, pWthi, pWtlo, bq, pQ);
    wsplit_kernel<<<gw, bw>>>(Wk, pWthi, pWtlo);
    gemm_bf3_kernel<<<gg, 256, GB_SMEM>>>(pAhi, pAlo, pWthi, pWtlo, bk, pK);
    wsplit_kernel<<<gw, bw>>>(Wv, pWthi, pWtlo);
    gemm_bf3_kernel<<<gg, 256, GB_SMEM>>>(pAhi, pAlo, pWthi, pWtlo, bv, pV);

    vround_kernel<<<(n4 + 255) / 256, 256>>>(pV, n4);
    lat_kernel<<<dim3(32, 16, 2), 256>>>(pQ, pK, Wql, bql, Wkl, bkl, pQL, pKL);
    attn2_kernel<<<dim3(16, 16, 2), 256, AT_SMEM_B>>>(pQL, pKL, pV, pAT);
    mixer_kernel<<<dim3(512), 256>>>(pAT, Wm, bm, pMX);

    xsplit_kernel<<<(n4 + 255) / 256, 256>>>(pMX, pAhi, pAlo, n4);
    wsplit_kernel<<<gw, bw>>>(Wo, pWthi, pWtlo);
    gemm_bf3_kernel<<<gg, 256, GB_SMEM>>>(pAhi, pAlo, pWthi, pWtlo, bo, out);
}

// round 6
// speedup vs baseline: 3.6852x; 1.0906x over previous
#include <cuda_runtime.h>
#include <cuda_bf16.h>
#include <mma.h>
#include <math.h>
#include <stdint.h>

using namespace nvcuda;

#define E_DIM 2048
#define B_SZ 2
#define S_LEN 2048
#define NH 16
#define DH 128
#define LDIM 64
#define M_ROWS 4096    /* B*S */

// ---------------- scratch (device globals; no runtime allocation) ----------------
__device__ __nv_bfloat16 g_Ahi[(size_t)M_ROWS * E_DIM];
__device__ __nv_bfloat16 g_Alo[(size_t)M_ROWS * E_DIM];
__device__ __nv_bfloat16 g_Qhi[(size_t)M_ROWS * E_DIM];
__device__ __nv_bfloat16 g_Qlo[(size_t)M_ROWS * E_DIM];
__device__ __nv_bfloat16 g_Khi[(size_t)M_ROWS * E_DIM];
__device__ __nv_bfloat16 g_Klo[(size_t)M_ROWS * E_DIM];
__device__ float g_V[(size_t)M_ROWS * E_DIM];
__device__ float g_QL[(size_t)B_SZ * NH * S_LEN * LDIM];
__device__ float g_KL[(size_t)B_SZ * NH * S_LEN * LDIM];
__device__ __nv_bfloat16 g_AThi[(size_t)B_SZ * NH * S_LEN * DH];
__device__ __nv_bfloat16 g_ATlo[(size_t)B_SZ * NH * S_LEN * DH];
__device__ __nv_bfloat16 g_W3hi[(size_t)3 * E_DIM * E_DIM];
__device__ __nv_bfloat16 g_W3lo[(size_t)3 * E_DIM * E_DIM];
__device__ __nv_bfloat16 g_Wthi[(size_t)E_DIM * E_DIM];
__device__ __nv_bfloat16 g_Wtlo[(size_t)E_DIM * E_DIM];
__device__ __nv_bfloat16 g_Wmhi[DH * DH];
__device__ __nv_bfloat16 g_Wmlo[DH * DH];
__device__ __nv_bfloat16 g_Wlhi[2 * LDIM * DH];
__device__ __nv_bfloat16 g_Wllo[2 * LDIM * DH];

__device__ __forceinline__ float gelu_tanh(float x) {
    const float c = 0.7978845608028654f;
    float x3 = x * x * x;
    return 0.5f * x * (1.f + tanhf(c * (x + 0.044715f * x3)));
}

__device__ __forceinline__ uint32_t smem_u32(const void* p) {
    uint32_t a;
    asm("{ .reg .u64 t; cvta.to.shared.u64 t, %1; cvt.u32.u64 %0, t; }" : "=r"(a) : "l"(p));
    return a;
}
#define CP_ASYNC16(dst, src) \
    asm volatile("cp.async.cg.shared.global [%0], [%1], 16;" :: "r"(dst), "l"(src))
#define CP_COMMIT() asm volatile("cp.async.commit_group;" ::: "memory")
#define CP_WAIT(n)  asm volatile("cp.async.wait_group %0;" :: "n"(n) : "memory")

__device__ __forceinline__ float tf32r(float x) {
    uint32_t u;
    asm("cvt.rna.tf32.f32 %0, %1;" : "=r"(u) : "f"(x));
    return __uint_as_float(u);
}

#define MMA_TF32(c, a0, a1, a2, a3, b0, b1) \
    asm volatile("mma.sync.aligned.m16n8k8.row.col.f32.tf32.tf32.f32 " \
        "{%0,%1,%2,%3}, {%4,%5,%6,%7}, {%8,%9}, {%0,%1,%2,%3};" \
        : "+f"((c)[0]), "+f"((c)[1]), "+f"((c)[2]), "+f"((c)[3]) \
        : "r"(a0), "r"(a1), "r"(a2), "r"(a3), "r"(b0), "r"(b1))

__device__ __forceinline__ void bf16_split(float v, __nv_bfloat16& h, __nv_bfloat16& l) {
    h = __float2bfloat16(v);
    l = __float2bfloat16(v - __bfloat162float(h));
}

// ================= prepass: bf16 hi/lo split (row-major) =================
__global__ __launch_bounds__(256) void xsplit_kernel(
    const float* __restrict__ src, __nv_bfloat16* __restrict__ hi, __nv_bfloat16* __restrict__ lo, int n4)
{
    int i = blockIdx.x * 256 + threadIdx.x;
    if (i >= n4) return;
    float4 v = reinterpret_cast<const float4*>(src)[i];
    __nv_bfloat16 h0, h1, h2, h3, l0, l1, l2, l3;
    bf16_split(v.x, h0, l0); bf16_split(v.y, h1, l1);
    bf16_split(v.z, h2, l2); bf16_split(v.w, h3, l3);
    __nv_bfloat162* ph = reinterpret_cast<__nv_bfloat162*>(hi) + i * 2;
    __nv_bfloat162* pl = reinterpret_cast<__nv_bfloat162*>(lo) + i * 2;
    ph[0] = __nv_bfloat162(h0, h1); ph[1] = __nv_bfloat162(h2, h3);
    pl[0] = __nv_bfloat162(l0, l1); pl[1] = __nv_bfloat162(l2, l3);
}

// ============ prepass: W [K,N] -> Wt hi/lo [N,K] bf16 transpose-split ============
__global__ __launch_bounds__(256) void wsplit_kernel(
    const float* __restrict__ W, __nv_bfloat16* __restrict__ hi, __nv_bfloat16* __restrict__ lo)
{
    __shared__ float t[32][33];
    int tx = threadIdx.x & 31, ty = threadIdx.x >> 5;
    int k0 = blockIdx.y * 32, n0 = blockIdx.x * 32;
#pragma unroll
    for (int j = 0; j < 4; j++)
        t[ty + j * 8][tx] = W[(size_t)(k0 + ty + j * 8) * E_DIM + n0 + tx];
    __syncthreads();
#pragma unroll
    for (int j = 0; j < 4; j++) {
        float v = t[tx][ty + j * 8];
        __nv_bfloat16 h, l;
        bf16_split(v, h, l);
        size_t o = (size_t)(n0 + ty + j * 8) * E_DIM + k0 + tx;
        hi[o] = h; lo[o] = l;
    }
}

// ====== prepass: small weights (Wm [128,128], Wql/Wkl [128,64]) -> [N,K] hi/lo ======
__global__ __launch_bounds__(256) void smallw_kernel(
    const float* __restrict__ Wm, const float* __restrict__ Wql, const float* __restrict__ Wkl,
    __nv_bfloat16* __restrict__ Wmhi, __nv_bfloat16* __restrict__ Wmlo,
    __nv_bfloat16* __restrict__ Wlhi, __nv_bfloat16* __restrict__ Wllo)
{
    int id = blockIdx.x;
    if (id == 0) {
        for (int i = threadIdx.x; i < DH * DH; i += 256) {
            int n = i >> 7, k = i & 127;
            __nv_bfloat16 h, l;
            bf16_split(Wm[k * DH + n], h, l);
            Wmhi[n * DH + k] = h; Wmlo[n * DH + k] = l;
        }
    } else {
        const float* W = (id == 1) ? Wql : Wkl;
        __nv_bfloat16* hi = Wlhi + (id - 1) * LDIM * DH;
        __nv_bfloat16* lo = Wllo + (id - 1) * LDIM * DH;
        for (int i = threadIdx.x; i < LDIM * DH; i += 256) {
            int n = i >> 7, k = i & 127;
            __nv_bfloat16 h, l;
            bf16_split(W[k * LDIM + n], h, l);
            hi[n * DH + k] = h; lo[n * DH + k] = l;
        }
    }
}

// ============ fused QKV bf16 3-term GEMM: [4096 x 6144 x 2048] ============
// Epilogue: Q/K columns -> bf16 hi/lo; V columns -> tf32-rounded float.
#define GB_STRIDE 72
#define GB_TILE_B (128 * GB_STRIDE * 2)
#define GB_STAGE (4 * GB_TILE_B)
#define GB_SMEM (2 * GB_STAGE)

__global__ __launch_bounds__(256) void gemm_qkv_kernel(
    const __nv_bfloat16* __restrict__ Ahi, const __nv_bfloat16* __restrict__ Alo,
    const __nv_bfloat16* __restrict__ Whi, const __nv_bfloat16* __restrict__ Wlo,
    const float* __restrict__ bq, const float* __restrict__ bk, const float* __restrict__ bv,
    __nv_bfloat16* __restrict__ Qhi, __nv_bfloat16* __restrict__ Qlo,
    __nv_bfloat16* __restrict__ Khi, __nv_bfloat16* __restrict__ Klo,
    float* __restrict__ Vout)
{
    extern __shared__ char smem[];
    uint32_t sb = smem_u32(smem);
    int tid = threadIdx.x, wid = tid >> 5, lane = tid & 31;
    int wr = wid >> 2, wc = wid & 3;
    int m0 = blockIdx.y * 128, n0 = blockIdx.x * 128;

    wmma::fragment<wmma::accumulator, 16, 16, 16, float> cf[4][2];
#pragma unroll
    for (int i = 0; i < 4; i++)
#pragma unroll
        for (int j = 0; j < 2; j++) wmma::fill_fragment(cf[i][j], 0.f);

    int row = tid >> 3;
    int jj = tid & 7;

#define LOAD_PIECE(p, srcptr, rbase)                                              \
    {                                                                             \
        _Pragma("unroll")                                                         \
        for (int q = 0; q < 4; q++) {                                             \
            int r = q * 32 + row;                                                 \
            const __nv_bfloat16* sp = (srcptr) + (size_t)((rbase) + r) * E_DIM + kcn * 64 + jj * 8; \
            uint32_t dp = sb + st * GB_STAGE + (p) * GB_TILE_B + r * (GB_STRIDE * 2) + jj * 16;     \
            CP_ASYNC16(dp, sp);                                                   \
        }                                                                         \
    }

    {
        int kcn = 0, st = 0;
        LOAD_PIECE(0, Ahi, m0) LOAD_PIECE(1, Alo, m0)
        LOAD_PIECE(2, Whi, n0) LOAD_PIECE(3, Wlo, n0)
        CP_COMMIT();
    }

    for (int kc = 0; kc < 32; kc++) {
        int s = kc & 1;
        if (kc < 31) {
            int kcn = kc + 1, st = s ^ 1;
            LOAD_PIECE(0, Ahi, m0) LOAD_PIECE(1, Alo, m0)
            LOAD_PIECE(2, Whi, n0) LOAD_PIECE(3, Wlo, n0)
            CP_COMMIT();
            CP_WAIT(1);
        } else {
            CP_WAIT(0);
        }
        __syncthreads();

        const __nv_bfloat16* Ah = reinterpret_cast<const __nv_bfloat16*>(smem + s * GB_STAGE);
        const __nv_bfloat16* Al = reinterpret_cast<const __nv_bfloat16*>(smem + s * GB_STAGE + GB_TILE_B);
        const __nv_bfloat16* Wh = reinterpret_cast<const __nv_bfloat16*>(smem + s * GB_STAGE + 2 * GB_TILE_B);
        const __nv_bfloat16* Wl = reinterpret_cast<const __nv_bfloat16*>(smem + s * GB_STAGE + 3 * GB_TILE_B);

#pragma unroll
        for (int ks = 0; ks < 4; ks++) {
            wmma::fragment<wmma::matrix_a, 16, 16, 16, __nv_bfloat16, wmma::row_major> ah[4], al[4];
            wmma::fragment<wmma::matrix_b, 16, 16, 16, __nv_bfloat16, wmma::col_major> bh[2], bl[2];
#pragma unroll
            for (int i = 0; i < 4; i++) {
                wmma::load_matrix_sync(ah[i], &Ah[(wr * 64 + i * 16) * GB_STRIDE + ks * 16], GB_STRIDE);
                wmma::load_matrix_sync(al[i], &Al[(wr * 64 + i * 16) * GB_STRIDE + ks * 16], GB_STRIDE);
            }
#pragma unroll
            for (int j = 0; j < 2; j++) {
                wmma::load_matrix_sync(bh[j], &Wh[(wc * 32 + j * 16) * GB_STRIDE + ks * 16], GB_STRIDE);
                wmma::load_matrix_sync(bl[j], &Wl[(wc * 32 + j * 16) * GB_STRIDE + ks * 16], GB_STRIDE);
            }
#pragma unroll
            for (int i = 0; i < 4; i++)
#pragma unroll
                for (int j = 0; j < 2; j++) {
                    wmma::mma_sync(cf[i][j], ah[i], bl[j], cf[i][j]);
                    wmma::mma_sync(cf[i][j], al[i], bh[j], cf[i][j]);
                    wmma::mma_sync(cf[i][j], ah[i], bh[j], cf[i][j]);
                }
        }
        __syncthreads();
    }
#undef LOAD_PIECE

    int which = n0 >> 11;           // 0=Q 1=K 2=V
    int nbase = n0 & 2047;
    const float* bptr = (which == 0) ? bq : ((which == 1) ? bk : bv);
    __nv_bfloat16* Hp = (which == 1) ? Khi : Qhi;
    __nv_bfloat16* Lp = (which == 1) ? Klo : Qlo;

    float* scratch = reinterpret_cast<float*>(smem) + wid * 320;
#pragma unroll
    for (int i = 0; i < 4; i++)
#pragma unroll
        for (int j = 0; j < 2; j++) {
            wmma::store_matrix_sync(scratch, cf[i][j], 20, wmma::mem_row_major);
            __syncwarp();
            int gr0 = m0 + wr * 64 + i * 16;
            int gcl = nbase + wc * 32 + j * 16;
#pragma unroll
            for (int e = lane; e < 256; e += 32) {
                int rr = e >> 4, cc = e & 15;
                float v = scratch[rr * 20 + cc] + bptr[gcl + cc];
                size_t o = (size_t)(gr0 + rr) * E_DIM + gcl + cc;
                if (which == 2) {
                    Vout[o] = tf32r(v);
                } else {
                    __nv_bfloat16 h, l;
                    bf16_split(v, h, l);
                    Hp[o] = h; Lp[o] = l;
                }
            }
            __syncwarp();
        }
}

// ============ output bf16 3-term E-GEMM: out = A @ Wo + bo ============
__global__ __launch_bounds__(256) void gemm_bf3_kernel(
    const __nv_bfloat16* __restrict__ Ahi, const __nv_bfloat16* __restrict__ Alo,
    const __nv_bfloat16* __restrict__ Whi, const __nv_bfloat16* __restrict__ Wlo,
    const float* __restrict__ bias, float* __restrict__ C)
{
    extern __shared__ char smem[];
    uint32_t sb = smem_u32(smem);
    int tid = threadIdx.x, wid = tid >> 5, lane = tid & 31;
    int wr = wid >> 2, wc = wid & 3;
    int m0 = blockIdx.y * 128, n0 = blockIdx.x * 128;

    wmma::fragment<wmma::accumulator, 16, 16, 16, float> cf[4][2];
#pragma unroll
    for (int i = 0; i < 4; i++)
#pragma unroll
        for (int j = 0; j < 2; j++) wmma::fill_fragment(cf[i][j], 0.f);

    int row = tid >> 3;
    int jj = tid & 7;

#define LOAD_PIECE(p, srcptr, rbase)                                              \
    {                                                                             \
        _Pragma("unroll")                                                         \
        for (int q = 0; q < 4; q++) {                                             \
            int r = q * 32 + row;                                                 \
            const __nv_bfloat16* sp = (srcptr) + (size_t)((rbase) + r) * E_DIM + kcn * 64 + jj * 8; \
            uint32_t dp = sb + st * GB_STAGE + (p) * GB_TILE_B + r * (GB_STRIDE * 2) + jj * 16;     \
            CP_ASYNC16(dp, sp);                                                   \
        }                                                                         \
    }

    {
        int kcn = 0, st = 0;
        LOAD_PIECE(0, Ahi, m0) LOAD_PIECE(1, Alo, m0)
        LOAD_PIECE(2, Whi, n0) LOAD_PIECE(3, Wlo, n0)
        CP_COMMIT();
    }

    for (int kc = 0; kc < 32; kc++) {
        int s = kc & 1;
        if (kc < 31) {
            int kcn = kc + 1, st = s ^ 1;
            LOAD_PIECE(0, Ahi, m0) LOAD_PIECE(1, Alo, m0)
            LOAD_PIECE(2, Whi, n0) LOAD_PIECE(3, Wlo, n0)
            CP_COMMIT();
            CP_WAIT(1);
        } else {
            CP_WAIT(0);
        }
        __syncthreads();

        const __nv_bfloat16* Ah = reinterpret_cast<const __nv_bfloat16*>(smem + s * GB_STAGE);
        const __nv_bfloat16* Al = reinterpret_cast<const __nv_bfloat16*>(smem + s * GB_STAGE + GB_TILE_B);
        const __nv_bfloat16* Wh = reinterpret_cast<const __nv_bfloat16*>(smem + s * GB_STAGE + 2 * GB_TILE_B);
        const __nv_bfloat16* Wl = reinterpret_cast<const __nv_bfloat16*>(smem + s * GB_STAGE + 3 * GB_TILE_B);

#pragma unroll
        for (int ks = 0; ks < 4; ks++) {
            wmma::fragment<wmma::matrix_a, 16, 16, 16, __nv_bfloat16, wmma::row_major> ah[4], al[4];
            wmma::fragment<wmma::matrix_b, 16, 16, 16, __nv_bfloat16, wmma::col_major> bh[2], bl[2];
#pragma unroll
            for (int i = 0; i < 4; i++) {
                wmma::load_matrix_sync(ah[i], &Ah[(wr * 64 + i * 16) * GB_STRIDE + ks * 16], GB_STRIDE);
                wmma::load_matrix_sync(al[i], &Al[(wr * 64 + i * 16) * GB_STRIDE + ks * 16], GB_STRIDE);
            }
#pragma unroll
            for (int j = 0; j < 2; j++) {
                wmma::load_matrix_sync(bh[j], &Wh[(wc * 32 + j * 16) * GB_STRIDE + ks * 16], GB_STRIDE);
                wmma::load_matrix_sync(bl[j], &Wl[(wc * 32 + j * 16) * GB_STRIDE + ks * 16], GB_STRIDE);
            }
#pragma unroll
            for (int i = 0; i < 4; i++)
#pragma unroll
                for (int j = 0; j < 2; j++) {
                    wmma::mma_sync(cf[i][j], ah[i], bl[j], cf[i][j]);
                    wmma::mma_sync(cf[i][j], al[i], bh[j], cf[i][j]);
                    wmma::mma_sync(cf[i][j], ah[i], bh[j], cf[i][j]);
                }
        }
        __syncthreads();
    }
#undef LOAD_PIECE

    float* scratch = reinterpret_cast<float*>(smem) + wid * 320;
#pragma unroll
    for (int i = 0; i < 4; i++)
#pragma unroll
        for (int j = 0; j < 2; j++) {
            wmma::store_matrix_sync(scratch, cf[i][j], 20, wmma::mem_row_major);
            __syncwarp();
            int gr0 = m0 + wr * 64 + i * 16;
            int gc0 = n0 + wc * 32 + j * 16;
#pragma unroll
            for (int e = lane; e < 256; e += 32) {
                int rr = e >> 4, cc = e & 15;
                float v = scratch[rr * 20 + cc] + bias[gc0 + cc];
                C[(size_t)(gr0 + rr) * E_DIM + gc0 + cc] = v;
            }
            __syncwarp();
        }
}

// ---------------- latent projection: bf16 3-term, elu+1, scale-fold, tf32 round ----------------
// grid (32, 16, 2), 256 threads; warp tile 32x32 (4x2 warps). K=128, N=64.
#define LB_AEL (128 * 136)
#define LB_BEL (64 * 136)
#define LB_SMEM ((2 * LB_AEL + 2 * LB_BEL) * 2)

__global__ __launch_bounds__(256) void lat_bf16_kernel(
    const __nv_bfloat16* __restrict__ Qhi, const __nv_bfloat16* __restrict__ Qlo,
    const __nv_bfloat16* __restrict__ Khi, const __nv_bfloat16* __restrict__ Klo,
    const __nv_bfloat16* __restrict__ Wlhi, const __nv_bfloat16* __restrict__ Wllo,
    const float* __restrict__ bql, const float* __restrict__ bkl,
    float* __restrict__ QL, float* __restrict__ KL)
{
    extern __shared__ __nv_bfloat16 smb[];
    __nv_bfloat16* Ah = smb;
    __nv_bfloat16* Al = Ah + LB_AEL;
    __nv_bfloat16* Bh = Al + LB_AEL;
    __nv_bfloat16* Bl = Bh + LB_BEL;

    int tid = threadIdx.x, w = tid >> 5, lane = tid & 31;
    int wr = w >> 1, wc = w & 1;
    int h = blockIdx.y, which = blockIdx.z;
    int m0 = blockIdx.x * 128;

    const __nv_bfloat16* Ash = which ? Khi : Qhi;
    const __nv_bfloat16* Asl = which ? Klo : Qlo;
    const __nv_bfloat16* Wsh = Wlhi + which * LDIM * DH;
    const __nv_bfloat16* Wsl = Wllo + which * LDIM * DH;
    const float* bl = which ? bkl : bql;
    float* C = which ? KL : QL;

#pragma unroll
    for (int i = 0; i < 8; i++) {
        int idx = i * 256 + tid;          // 2048 x 16B per piece
        int r = idx >> 4, c8 = idx & 15;
        *reinterpret_cast<uint4*>(&Ah[r * 136 + c8 * 8]) =
            *reinterpret_cast<const uint4*>(&Ash[(size_t)(m0 + r) * E_DIM + h * DH + c8 * 8]);
        *reinterpret_cast<uint4*>(&Al[r * 136 + c8 * 8]) =
            *reinterpret_cast<const uint4*>(&Asl[(size_t)(m0 + r) * E_DIM + h * DH + c8 * 8]);
    }
#pragma unroll
    for (int i = 0; i < 4; i++) {
        int idx = i * 256 + tid;          // 1024 x 16B per piece
        int r = idx >> 4, c8 = idx & 15;
        *reinterpret_cast<uint4*>(&Bh[r * 136 + c8 * 8]) =
            *reinterpret_cast<const uint4*>(&Wsh[r * DH + c8 * 8]);
        *reinterpret_cast<uint4*>(&Bl[r * 136 + c8 * 8]) =
            *reinterpret_cast<const uint4*>(&Wsl[r * DH + c8 * 8]);
    }
    __syncthreads();

    wmma::fragment<wmma::accumulator, 16, 16, 16, float> cf[2][2];
#pragma unroll
    for (int i = 0; i < 2; i++)
#pragma unroll
        for (int j = 0; j < 2; j++) wmma::fill_fragment(cf[i][j], 0.f);

#pragma unroll
    for (int ks = 0; ks < 8; ks++) {
        wmma::fragment<wmma::matrix_a, 16, 16, 16, __nv_bfloat16, wmma::row_major> ah[2], al2[2];
        wmma::fragment<wmma::matrix_b, 16, 16, 16, __nv_bfloat16, wmma::col_major> bh[2], bl2[2];
#pragma unroll
        for (int i = 0; i < 2; i++) {
            wmma::load_matrix_sync(ah[i], &Ah[(wr * 32 + i * 16) * 136 + ks * 16], 136);
            wmma::load_matrix_sync(al2[i], &Al[(wr * 32 + i * 16) * 136 + ks * 16], 136);
        }
#pragma unroll
        for (int j = 0; j < 2; j++) {
            wmma::load_matrix_sync(bh[j], &Bh[(wc * 32 + j * 16) * 136 + ks * 16], 136);
            wmma::load_matrix_sync(bl2[j], &Bl[(wc * 32 + j * 16) * 136 + ks * 16], 136);
        }
#pragma unroll
        for (int i = 0; i < 2; i++)
#pragma unroll
            for (int j = 0; j < 2; j++) {
                wmma::mma_sync(cf[i][j], ah[i], bl2[j], cf[i][j]);
                wmma::mma_sync(cf[i][j], al2[i], bh[j], cf[i][j]);
                wmma::mma_sync(cf[i][j], ah[i], bh[j], cf[i][j]);
            }
    }
    __syncthreads();

    float* scratch = reinterpret_cast<float*>(smb) + w * 320;
    float qscale = which ? 1.0f : 0.125f;
#pragma unroll
    for (int i = 0; i < 2; i++)
#pragma unroll
        for (int j = 0; j < 2; j++) {
            wmma::store_matrix_sync(scratch, cf[i][j], 20, wmma::mem_row_major);
            __syncwarp();
#pragma unroll
            for (int e = lane; e < 256; e += 32) {
                int rr = e >> 4, cc = e & 15;
                int gr = m0 + wr * 32 + i * 16 + rr;
                int gc = wc * 32 + j * 16 + cc;
                float v = scratch[rr * 20 + cc] + bl[gc];
                v = (v > 0.f) ? (v + 1.f) : expf(v);
                v = tf32r(v * qscale);
                int b = gr >> 11;
                int s = gr & 2047;
                C[((size_t)(b * NH + h) * S_LEN + s) * LDIM + gc] = v;
            }
            __syncwarp();
        }
}

// ================ single-pass flash attention (raw mma.sync tf32) ================
#define AT_QS 0
#define AT_KS (128 * 68)
#define AT_VS (AT_KS + 2 * 64 * 68)
#define AT_PS (AT_VS + 2 * 64 * 136)
#define AT_TOT (AT_PS + 128 * 68)
#define AT_SMEM_B (AT_TOT * 4)

__global__ __launch_bounds__(256) void attn2_kernel(
    const float* __restrict__ QL, const float* __restrict__ KL,
    const float* __restrict__ V,
    __nv_bfloat16* __restrict__ OUThi, __nv_bfloat16* __restrict__ OUTlo)
{
    extern __shared__ float sm[];
    float* qs  = sm;
    float* ksb = sm + AT_KS;
    float* vsb = sm + AT_VS;
    float* Ps  = sm + AT_PS;
    uint32_t sbase = smem_u32(sm);

    int tid = threadIdx.x, w = tid >> 5, lane = tid & 31;
    int g = lane >> 2, t = lane & 3;
    int wrow = w * 16;
    int qb = blockIdx.x, h = blockIdx.y, b = blockIdx.z;
    int bh = b * NH + h;

    {
        const float* qsrc = QL + ((size_t)bh * S_LEN + qb * 128) * LDIM;
#pragma unroll
        for (int i = 0; i < 8; i++) {
            int idx = i * 256 + tid;
            int r = idx >> 4, c4 = idx & 15;
            float4 v4 = *reinterpret_cast<const float4*>(&qsrc[r * LDIM + c4 * 4]);
            *reinterpret_cast<float4*>(&qs[r * 68 + c4 * 4]) = v4;
        }
    }

#define AT_PREFETCH(ci, bf)                                                           \
    {                                                                                 \
        _Pragma("unroll")                                                             \
        for (int i = 0; i < 4; i++) {                                                 \
            int idx = i * 256 + tid;                                                  \
            int r = idx >> 4, c = idx & 15;                                           \
            uint32_t dp = sbase + (uint32_t)(AT_KS + (bf) * 64 * 68 + r * 68 + c * 4) * 4; \
            CP_ASYNC16(dp, KL + ((size_t)bh * S_LEN + (ci) * 64 + r) * LDIM + c * 4); \
        }                                                                             \
        _Pragma("unroll")                                                             \
        for (int i = 0; i < 8; i++) {                                                 \
            int idx = i * 256 + tid;                                                  \
            int r = idx >> 5, c = idx & 31;                                           \
            uint32_t dp = sbase + (uint32_t)(AT_VS + (bf) * 64 * 136 + r * 136 + c * 4) * 4; \
            CP_ASYNC16(dp, V + ((size_t)(b * S_LEN + (ci) * 64 + r)) * E_DIM + h * DH + c * 4); \
        }                                                                             \
    }

    AT_PREFETCH(0, 0)
    CP_COMMIT();

    float ot[16][4], ob[16][4];
#pragma unroll
    for (int n = 0; n < 16; n++)
#pragma unroll
        for (int j = 0; j < 4; j++) { ot[n][j] = 0.f; ob[n][j] = 0.f; }
    float l0 = 0.f, l1 = 0.f;

    for (int ci = 0; ci < 32; ci++) {
        int buf = ci & 1;
        CP_WAIT(0);
        __syncthreads();
        if (ci < 31) {
            AT_PREFETCH(ci + 1, buf ^ 1)
            CP_COMMIT();
        }
        const float* ks  = ksb + buf * 64 * 68;
        const float* vsx = vsb + buf * 64 * 136;

        float c[8][4];
#pragma unroll
        for (int n = 0; n < 8; n++)
#pragma unroll
            for (int j = 0; j < 4; j++) c[n][j] = 0.f;
#pragma unroll
        for (int kk = 0; kk < 8; kk++) {
            int ko = kk * 8 + t;
            uint32_t a0 = __float_as_uint(qs[(wrow + g) * 68 + ko]);
            uint32_t a1 = __float_as_uint(qs[(wrow + 8 + g) * 68 + ko]);
            uint32_t a2 = __float_as_uint(qs[(wrow + g) * 68 + ko + 4]);
            uint32_t a3 = __float_as_uint(qs[(wrow + 8 + g) * 68 + ko + 4]);
#pragma unroll
            for (int n = 0; n < 8; n++) {
                uint32_t b0 = __float_as_uint(ks[(n * 8 + g) * 68 + ko]);
                uint32_t b1 = __float_as_uint(ks[(n * 8 + g) * 68 + ko + 4]);
                MMA_TF32(c[n], a0, a1, a2, a3, b0, b1);
            }
        }
#pragma unroll
        for (int n = 0; n < 8; n++) {
            float p0 = __expf(c[n][0]), p1 = __expf(c[n][1]);
            float p2 = __expf(c[n][2]), p3 = __expf(c[n][3]);
            l0 += p0 + p1; l1 += p2 + p3;
            float2 u0 = make_float2(tf32r(p0), tf32r(p1));
            float2 u1 = make_float2(tf32r(p2), tf32r(p3));
            *reinterpret_cast<float2*>(&Ps[(wrow + g) * 68 + n * 8 + 2 * t]) = u0;
            *reinterpret_cast<float2*>(&Ps[(wrow + 8 + g) * 68 + n * 8 + 2 * t]) = u1;
        }
        __syncthreads();
#pragma unroll
        for (int kk = 0; kk < 8; kk++) {
            int ko = kk * 8 + t;
            uint32_t a0 = __float_as_uint(Ps[(wrow + g) * 68 + ko]);
            uint32_t a1 = __float_as_uint(Ps[(wrow + 8 + g) * 68 + ko]);
            uint32_t a2 = __float_as_uint(Ps[(wrow + g) * 68 + ko + 4]);
            uint32_t a3 = __float_as_uint(Ps[(wrow + 8 + g) * 68 + ko + 4]);
#pragma unroll
            for (int n = 0; n < 16; n++) {
                uint32_t b0 = __float_as_uint(vsx[ko * 136 + n * 8 + g]);
                uint32_t b1 = __float_as_uint(vsx[(ko + 4) * 136 + n * 8 + g]);
                MMA_TF32(ob[n], a0, a1, a2, a3, b0, b1);
            }
        }
        if ((ci & 7) == 7) {
            l0 += __shfl_xor_sync(0xFFFFFFFFu, l0, 1);
            l0 += __shfl_xor_sync(0xFFFFFFFFu, l0, 2);
            l1 += __shfl_xor_sync(0xFFFFFFFFu, l1, 1);
            l1 += __shfl_xor_sync(0xFFFFFFFFu, l1, 2);
            float i0 = 1.f / l0, i1 = 1.f / l1;
#pragma unroll
            for (int n = 0; n < 16; n++) {
                ot[n][0] += ob[n][0] * i0; ot[n][1] += ob[n][1] * i0;
                ot[n][2] += ob[n][2] * i1; ot[n][3] += ob[n][3] * i1;
                ob[n][0] = 0.f; ob[n][1] = 0.f; ob[n][2] = 0.f; ob[n][3] = 0.f;
            }
            l0 = 0.f; l1 = 0.f;
        }
    }
#undef AT_PREFETCH

    // write bf16 hi/lo (mixer input) at [BH*S, 128]
    {
        size_t row0 = (size_t)bh * S_LEN + qb * 128 + wrow + g;
#pragma unroll
        for (int n = 0; n < 16; n++) {
            __nv_bfloat16 h0, l0b, h1, l1b;
            bf16_split(ot[n][0], h0, l0b); bf16_split(ot[n][1], h1, l1b);
            size_t o0 = row0 * DH + n * 8 + 2 * t;
            *reinterpret_cast<__nv_bfloat162*>(&OUThi[o0]) = __nv_bfloat162(h0, h1);
            *reinterpret_cast<__nv_bfloat162*>(&OUTlo[o0]) = __nv_bfloat162(l0b, l1b);
            bf16_split(ot[n][2], h0, l0b); bf16_split(ot[n][3], h1, l1b);
            size_t o1 = (row0 + 8) * DH + n * 8 + 2 * t;
            *reinterpret_cast<__nv_bfloat162*>(&OUThi[o1]) = __nv_bfloat162(h0, h1);
            *reinterpret_cast<__nv_bfloat162*>(&OUTlo[o1]) = __nv_bfloat162(l0b, l1b);
        }
    }
}

// ---------------- mixer: gelu(AT @ Wm + bm), bf16 3-term, fused transpose+split ----------------
// grid 512, 256 threads; warp tile 64x32 (2x4 warps). K=128, N=128.
#define MX_AEL (128 * 136)
#define MX_SMEM (4 * MX_AEL * 2)

__global__ __launch_bounds__(256) void mixer_bf16_kernel(
    const __nv_bfloat16* __restrict__ AThi, const __nv_bfloat16* __restrict__ ATlo,
    const __nv_bfloat16* __restrict__ Wmhi, const __nv_bfloat16* __restrict__ Wmlo,
    const float* __restrict__ bm,
    __nv_bfloat16* __restrict__ Ohi, __nv_bfloat16* __restrict__ Olo)
{
    extern __shared__ __nv_bfloat16 smb[];
    __nv_bfloat16* Ah = smb;
    __nv_bfloat16* Al = Ah + MX_AEL;
    __nv_bfloat16* Bh = Al + MX_AEL;
    __nv_bfloat16* Bl = Bh + MX_AEL;

    int tid = threadIdx.x, w = tid >> 5, lane = tid & 31;
    int wr = w >> 2, wc = w & 3;
    int m0 = blockIdx.x * 128;

#pragma unroll
    for (int i = 0; i < 8; i++) {
        int idx = i * 256 + tid;
        int r = idx >> 4, c8 = idx & 15;
        *reinterpret_cast<uint4*>(&Ah[r * 136 + c8 * 8]) =
            *reinterpret_cast<const uint4*>(&AThi[(size_t)(m0 + r) * DH + c8 * 8]);
        *reinterpret_cast<uint4*>(&Al[r * 136 + c8 * 8]) =
            *reinterpret_cast<const uint4*>(&ATlo[(size_t)(m0 + r) * DH + c8 * 8]);
        *reinterpret_cast<uint4*>(&Bh[r * 136 + c8 * 8]) =
            *reinterpret_cast<const uint4*>(&Wmhi[r * DH + c8 * 8]);
        *reinterpret_cast<uint4*>(&Bl[r * 136 + c8 * 8]) =
            *reinterpret_cast<const uint4*>(&Wmlo[r * DH + c8 * 8]);
    }
    __syncthreads();

    wmma::fragment<wmma::accumulator, 16, 16, 16, float> cf[4][2];
#pragma unroll
    for (int i = 0; i < 4; i++)
#pragma unroll
        for (int j = 0; j < 2; j++) wmma::fill_fragment(cf[i][j], 0.f);

#pragma unroll
    for (int ks = 0; ks < 8; ks++) {
        wmma::fragment<wmma::matrix_a, 16, 16, 16, __nv_bfloat16, wmma::row_major> ah[4], al2[4];
        wmma::fragment<wmma::matrix_b, 16, 16, 16, __nv_bfloat16, wmma::col_major> bh[2], bl2[2];
#pragma unroll
        for (int i = 0; i < 4; i++) {
            wmma::load_matrix_sync(ah[i], &Ah[(wr * 64 + i * 16) * 136 + ks * 16], 136);
            wmma::load_matrix_sync(al2[i], &Al[(wr * 64 + i * 16) * 136 + ks * 16], 136);
        }
#pragma unroll
        for (int j = 0; j < 2; j++) {
            wmma::load_matrix_sync(bh[j], &Bh[(wc * 32 + j * 16) * 136 + ks * 16], 136);
            wmma::load_matrix_sync(bl2[j], &Bl[(wc * 32 + j * 16) * 136 + ks * 16], 136);
        }
#pragma unroll
        for (int i = 0; i < 4; i++)
#pragma unroll
            for (int j = 0; j < 2; j++) {
                wmma::mma_sync(cf[i][j], ah[i], bl2[j], cf[i][j]);
                wmma::mma_sync(cf[i][j], al2[i], bh[j], cf[i][j]);
                wmma::mma_sync(cf[i][j], ah[i], bh[j], cf[i][j]);
            }
    }
    __syncthreads();

    float* scratch = reinterpret_cast<float*>(smb) + w * 320;
#pragma unroll
    for (int i = 0; i < 4; i++)
#pragma unroll
        for (int j = 0; j < 2; j++) {
            wmma::store_matrix_sync(scratch, cf[i][j], 20, wmma::mem_row_major);
            __syncwarp();
#pragma unroll
            for (int e = lane; e < 256; e += 32) {
                int rr = e >> 4, cc = e & 15;
                int rg = m0 + wr * 64 + i * 16 + rr;
                int gc = wc * 32 + j * 16 + cc;
                float v = gelu_tanh(scratch[rr * 20 + cc] + bm[gc]);
                int bb = rg >> 15;
                int hh = (rg >> 11) & 15;
                int ss = rg & 2047;
                size_t o = ((size_t)(bb * S_LEN + ss)) * E_DIM + hh * DH + gc;
                __nv_bfloat16 hv, lv;
                bf16_split(v, hv, lv);
                Ohi[o] = hv; Olo[o] = lv;
            }
            __syncwarp();
        }
}

// ---------------- launch ----------------
extern "C" void kernel_launch(void* const* d_in, const int* in_sizes, int n_in,
                              void* d_out, int out_size)
{
    const float* x   = (const float*)d_in[0];
    const float* Wq  = (const float*)d_in[1];
    const float* bq  = (const float*)d_in[2];
    const float* Wk  = (const float*)d_in[3];
    const float* bk  = (const float*)d_in[4];
    const float* Wv  = (const float*)d_in[5];
    const float* bv  = (const float*)d_in[6];
    const float* Wo  = (const float*)d_in[7];
    const float* bo  = (const float*)d_in[8];
    const float* Wql = (const float*)d_in[9];
    const float* bql = (const float*)d_in[10];
    const float* Wkl = (const float*)d_in[11];
    const float* bkl = (const float*)d_in[12];
    const float* Wm  = (const float*)d_in[13];
    const float* bm  = (const float*)d_in[14];
    float* out = (float*)d_out;

    float *pV, *pQL, *pKL;
    __nv_bfloat16 *pAhi, *pAlo, *pQhi, *pQlo, *pKhi, *pKlo;
    __nv_bfloat16 *pW3hi, *pW3lo, *pWthi, *pWtlo;
    __nv_bfloat16 *pAThi, *pATlo, *pWmhi, *pWmlo, *pWlhi, *pWllo;
    cudaGetSymbolAddress((void**)&pV,   g_V);
    cudaGetSymbolAddress((void**)&pQL,  g_QL);
    cudaGetSymbolAddress((void**)&pKL,  g_KL);
    cudaGetSymbolAddress((void**)&pAhi, g_Ahi);
    cudaGetSymbolAddress((void**)&pAlo, g_Alo);
    cudaGetSymbolAddress((void**)&pQhi, g_Qhi);
    cudaGetSymbolAddress((void**)&pQlo, g_Qlo);
    cudaGetSymbolAddress((void**)&pKhi, g_Khi);
    cudaGetSymbolAddress((void**)&pKlo, g_Klo);
    cudaGetSymbolAddress((void**)&pW3hi, g_W3hi);
    cudaGetSymbolAddress((void**)&pW3lo, g_W3lo);
    cudaGetSymbolAddress((void**)&pWthi, g_Wthi);
    cudaGetSymbolAddress((void**)&pWtlo, g_Wtlo);
    cudaGetSymbolAddress((void**)&pAThi, g_AThi);
    cudaGetSymbolAddress((void**)&pATlo, g_ATlo);
    cudaGetSymbolAddress((void**)&pWmhi, g_Wmhi);
    cudaGetSymbolAddress((void**)&pWmlo, g_Wmlo);
    cudaGetSymbolAddress((void**)&pWlhi, g_Wlhi);
    cudaGetSymbolAddress((void**)&pWllo, g_Wllo);

    cudaFuncSetAttribute(attn2_kernel, cudaFuncAttributeMaxDynamicSharedMemorySize, AT_SMEM_B);
    cudaFuncSetAttribute(gemm_qkv_kernel, cudaFuncAttributeMaxDynamicSharedMemorySize, GB_SMEM);
    cudaFuncSetAttribute(gemm_bf3_kernel, cudaFuncAttributeMaxDynamicSharedMemorySize, GB_SMEM);
    cudaFuncSetAttribute(lat_bf16_kernel, cudaFuncAttributeMaxDynamicSharedMemorySize, LB_SMEM);
    cudaFuncSetAttribute(mixer_bf16_kernel, cudaFuncAttributeMaxDynamicSharedMemorySize, MX_SMEM);

    const int n4 = (M_ROWS * E_DIM) / 4;
    dim3 gw(64, 64), bw(256);

    xsplit_kernel<<<(n4 + 255) / 256, 256>>>(x, pAhi, pAlo, n4);
    wsplit_kernel<<<gw, bw>>>(Wq, pW3hi, pW3lo);
    wsplit_kernel<<<gw, bw>>>(Wk, pW3hi + (size_t)E_DIM * E_DIM, pW3lo + (size_t)E_DIM * E_DIM);
    wsplit_kernel<<<gw, bw>>>(Wv, pW3hi + (size_t)2 * E_DIM * E_DIM, pW3lo + (size_t)2 * E_DIM * E_DIM);
    smallw_kernel<<<3, 256>>>(Wm, Wql, Wkl, pWmhi, pWmlo, pWlhi, pWllo);

    gemm_qkv_kernel<<<dim3(48, 32), 256, GB_SMEM>>>(
        pAhi, pAlo, pW3hi, pW3lo, bq, bk, bv, pQhi, pQlo, pKhi, pKlo, pV);

    lat_bf16_kernel<<<dim3(32, 16, 2), 256, LB_SMEM>>>(
        pQhi, pQlo, pKhi, pKlo, pWlhi, pWllo, bql, bkl, pQL, pKL);

    attn2_kernel<<<dim3(16, 16, 2), 256, AT_SMEM_B>>>(pQL, pKL, pV, pAThi, pATlo);

    mixer_bf16_kernel<<<dim3(512), 256, MX_SMEM>>>(pAThi, pATlo, pWmhi, pWmlo, bm, pAhi, pAlo);

    wsplit_kernel<<<gw, bw>>>(Wo, pWthi, pWtlo);
    gemm_bf3_kernel<<<dim3(16, 32), 256, GB_SMEM>>>(pAhi, pAlo, pWthi, pWtlo, bo, out);
}